// round 11
// baseline (speedup 1.0000x reference)
#include <cuda_runtime.h>
#include <cuda_bf16.h>
#include <math.h>
#include <stdint.h>

#define N_NODE 20000
#define EMB 100
#define BATCH 512
#define SEQ 50
#define N_LAYERS 2
#define INV_TEMP 10.0f
#define W_KF 10.0f
#define TOPK 10
#define CL_WF 100.0f
#define EPSN 1e-12f
#define EMAX 345000

// mma.sync cl gemm tiling
#define KPAD 112                // K padded to 7*16
#define KC 7
#define CLM 128                 // rows per CTA
#define CLN 64                  // cols per tile
#define NBLK 157                // ceil(20000/128)
#define ROWS_PAD (NBLK*CLM)     // 20096
#define NTILES 313              // ceil(20000/64)
#define BROW 120                // smem row stride in halves (240B)
#define NQ 16
#define NITEMS (NBLK*NQ)        // 2512
#define CLGRID 296
#define A_BYTES (CLM*BROW*2)    // 30720
#define B_BYTES (CLN*BROW*2)    // 15360
#define CL_SMEM (A_BYTES + 2*B_BYTES)  // 61440

// ---------------- scratch ----------------
__device__ float g_colsum[N_NODE];
__device__ int   g_cnt[N_NODE];
__device__ int   g_rowptr[N_NODE+1];
__device__ int   g_cursor[N_NODE];
__device__ int   g_ecol[EMAX];
__device__ float g_eval[EMAX];
__device__ int   g_work;
__device__ float g_x[N_NODE*EMB];
__device__ float g_y[N_NODE*EMB];
__device__ float g_final[N_NODE*EMB];
__device__ float g_item[N_NODE*EMB];
__device__ float g_itemn[N_NODE*EMB];
__device__ float g_s[N_NODE];
__device__ float g_amax;
__device__ float g_asum;
__device__ float g_wT[N_LAYERS*EMB*EMB];
__device__ float g_glu1T[EMB*EMB];
__device__ float g_glu2T[EMB*EMB];
__device__ float g_sess[BATCH*EMB];
__device__ float g_sessn[BATCH*EMB];
__device__ float g_posw[SEQ*EMB];
__device__ float g_qtk[(size_t)ROWS_PAD*NQ*TOPK];
__device__ __align__(16) __nv_bfloat16 g_bf16[(size_t)ROWS_PAD*KPAD];

// ---------------- helpers ----------------
__device__ __forceinline__ float warp_sum(float v) {
    #pragma unroll
    for (int o = 16; o > 0; o >>= 1) v += __shfl_xor_sync(0xffffffffu, v, o);
    return v;
}

__device__ __forceinline__ void topk_insert(float (&tk)[TOPK], float v) {
    if (v > tk[TOPK-1]) {
        tk[TOPK-1] = v;
        #pragma unroll
        for (int i = TOPK-1; i > 0; --i) {
            if (tk[i] > tk[i-1]) { float tmp = tk[i-1]; tk[i-1] = tk[i]; tk[i] = tmp; }
        }
    }
}

// chain-free group scan: independent max-tree on the hot path, sorted insert
// only inside a (warp-divergent but rare-ish) taken branch.
__device__ __forceinline__ void scan4(float (&tk)[TOPK], float &thr,
                                      float a, float b, float c, float d) {
    float m01 = fmaxf(a, b), m23 = fmaxf(c, d);
    float gm = fmaxf(m01, m23);
    if (gm > thr) {
        if (a > thr) topk_insert(tk, a);
        if (b > thr) topk_insert(tk, b);
        if (c > thr) topk_insert(tk, c);
        if (d > thr) topk_insert(tk, d);
        thr = tk[TOPK-1];
    }
}

// ---------------- init ----------------
__global__ void k_init(const float* __restrict__ emb, float* __restrict__ out, int out_size) {
    int stride = gridDim.x * blockDim.x;
    int i0 = blockIdx.x * blockDim.x + threadIdx.x;
    for (int i = i0; i < N_NODE*EMB; i += stride) {
        float v = emb[i];
        g_x[i] = v;
        g_final[i] = v;
        if (i < N_NODE) { g_colsum[i] = 0.0f; g_cnt[i] = 0; }
    }
    for (int i = i0; i < (ROWS_PAD - N_NODE)*KPAD; i += stride)
        g_bf16[(size_t)N_NODE*KPAD + i] = __float2bfloat16(0.0f);
    if (i0 == 0) { out[0] = 0.0f; out[out_size-1] = 0.0f; g_work = 0; }
}

// ---------------- transpose weights ----------------
__global__ void k_transpose(const float* __restrict__ w_item,
                            const float* __restrict__ glu1,
                            const float* __restrict__ glu2) {
    int i = blockIdx.x * blockDim.x + threadIdx.x;
    if (i < N_LAYERS*EMB*EMB) {
        int l = i / (EMB*EMB);
        int r = i - l*(EMB*EMB);
        int j = r / EMB, k = r - j*EMB;
        g_wT[l*EMB*EMB + j*EMB + k] = w_item[l*EMB*EMB + k*EMB + j];
    }
    if (i < EMB*EMB) {
        int j = i / EMB, k = i - j*EMB;
        g_glu1T[j*EMB + k] = glu1[k*EMB + j];
        g_glu2T[j*EMB + k] = glu2[k*EMB + j];
    }
}

// ---------------- posW ----------------
__global__ void k_posw(const float* __restrict__ pos, const float* __restrict__ w1) {
    int l = blockIdx.x, t = threadIdx.x;
    if (t < EMB) {
        float acc = 0.0f;
        for (int j = 0; j < EMB; ++j) acc += pos[l*EMB + j] * w1[j*EMB + t];
        g_posw[l*EMB + t] = acc;
    }
}

// ---------------- edge pass: column sums + row degrees ----------------
__global__ void k_prep(const int* __restrict__ row, const int* __restrict__ col,
                       const float* __restrict__ vals, int E) {
    int e = blockIdx.x * blockDim.x + threadIdx.x;
    if (e < E) {
        atomicAdd(&g_colsum[col[e]], vals[e]);
        atomicAdd(&g_cnt[row[e]], 1);
    }
}

// ---------------- prefix sum -> rowptr ----------------
__global__ void k_scan() {
    __shared__ int sh[1024];
    int t = threadIdx.x;
    const int CH = 20;
    int local[CH];
    int s = 0;
    #pragma unroll
    for (int i = 0; i < CH; ++i) {
        int idx = t*CH + i;
        int c = (idx < N_NODE) ? g_cnt[idx] : 0;
        local[i] = s; s += c;
    }
    sh[t] = s; __syncthreads();
    for (int off = 1; off < 1024; off <<= 1) {
        int v = (t >= off) ? sh[t-off] : 0;
        __syncthreads();
        if (t >= off) sh[t] += v;
        __syncthreads();
    }
    int base = (t == 0) ? 0 : sh[t-1];
    #pragma unroll
    for (int i = 0; i < CH; ++i) {
        int idx = t*CH + i;
        if (idx < N_NODE) {
            int p = base + local[i];
            g_rowptr[idx] = p;
            g_cursor[idx] = p;
        }
    }
    if (t == 1023) g_rowptr[N_NODE] = sh[1023];
}

// ---------------- scatter edges into CSR ----------------
__global__ void k_scatter(const int* __restrict__ row, const int* __restrict__ col,
                          const float* __restrict__ vals, int E) {
    int e = blockIdx.x * blockDim.x + threadIdx.x;
    if (e >= E) return;
    int c = col[e], r = row[e];
    float v = vals[e] / g_colsum[c];
    int p = atomicAdd(&g_cursor[r], 1);
    g_ecol[p] = c;
    g_eval[p] = v;
}

// ---------------- attention scores ----------------
__global__ void k_att_score(const float* __restrict__ attw, const float* __restrict__ attb) {
    int gw = (blockIdx.x * blockDim.x + threadIdx.x) >> 5;
    int lane = threadIdx.x & 31;
    if (gw >= N_NODE) return;
    const float* xr = g_x + gw*EMB;
    float acc = 0.0f;
    for (int k = lane; k < EMB; k += 32) acc += xr[k] * attw[k];
    acc = warp_sum(acc);
    if (lane == 0) g_s[gw] = acc + attb[0];
}

// ---------------- softmax reduce ----------------
__global__ void k_softmax_reduce() {
    __shared__ float sh[1024];
    int t = threadIdx.x;
    float m = -INFINITY;
    for (int i = t; i < N_NODE; i += 1024) m = fmaxf(m, g_s[i]);
    sh[t] = m; __syncthreads();
    for (int s = 512; s > 0; s >>= 1) { if (t < s) sh[t] = fmaxf(sh[t], sh[t+s]); __syncthreads(); }
    float mx = sh[0]; __syncthreads();
    float sum = 0.0f;
    for (int i = t; i < N_NODE; i += 1024) sum += __expf(g_s[i] - mx);
    sh[t] = sum; __syncthreads();
    for (int s = 512; s > 0; s >>= 1) { if (t < s) sh[t] += sh[t+s]; __syncthreads(); }
    if (t == 0) { g_amax = mx; g_asum = sh[0]; }
}

// ---------------- y = (x @ W^T) * att  (WT staged in smem) ----------------
__global__ void k_lin_att(int layer) {
    extern __shared__ float sm_la[];
    float* WT = sm_la;            // [100][100]
    float* xs = sm_la + EMB*EMB;  // [64][100]
    int base = blockIdx.x * 64;
    int t = threadIdx.x;
    int nvalid = min(64, N_NODE - base);
    const float* WTg = g_wT + layer*EMB*EMB;
    for (int i = t; i < EMB*EMB; i += 256) WT[i] = WTg[i];
    for (int i = t; i < nvalid*EMB; i += 256) xs[i] = g_x[base*EMB + i];
    __syncthreads();
    float inv = 1.0f / g_asum;
    float mx  = g_amax;
    int npairs = nvalid * 25;
    for (int p = t; p < npairs; p += 256) {
        int n = p / 25, k4 = p - n*25;
        float a0 = 0.f, a1 = 0.f, a2 = 0.f, a3 = 0.f;
        const float* xr = xs + n*EMB;
        #pragma unroll 4
        for (int j = 0; j < EMB; ++j) {
            float xv = xr[j];
            float4 wv = *(const float4*)&WT[j*EMB + k4*4];
            a0 += xv*wv.x; a1 += xv*wv.y; a2 += xv*wv.z; a3 += xv*wv.w;
        }
        float att = __expf(g_s[base + n] - mx) * inv;
        float4 o = make_float4(a0*att, a1*att, a2*att, a3*att);
        *(float4*)(g_y + (size_t)(base + n)*EMB + k4*4) = o;
    }
}

// ---------------- CSR SpMM fused with l2norm + final accumulate ----------------
__global__ void k_spmm_csr() {
    int gw = (blockIdx.x * blockDim.x + threadIdx.x) >> 5;
    int lane = threadIdx.x & 31;
    if (gw >= N_NODE) return;
    int s = g_rowptr[gw], e = g_rowptr[gw+1];
    bool act = lane < 25;
    float4 acc = make_float4(0.f, 0.f, 0.f, 0.f);
    for (int i = s; i < e; ++i) {
        int c = g_ecol[i];
        float v = g_eval[i];
        if (act) {
            float4 yv = *(const float4*)(g_y + (size_t)c*EMB + lane*4);
            acc.x += v*yv.x; acc.y += v*yv.y; acc.z += v*yv.z; acc.w += v*yv.w;
        }
    }
    float ss = acc.x*acc.x + acc.y*acc.y + acc.z*acc.z + acc.w*acc.w;
    ss = warp_sum(ss);
    float invn = 1.0f / fmaxf(sqrtf(ss), EPSN);
    if (act) {
        float4 nv = make_float4(acc.x*invn, acc.y*invn, acc.z*invn, acc.w*invn);
        *(float4*)(g_x + (size_t)gw*EMB + lane*4) = nv;
        float4 f = *(const float4*)(g_final + (size_t)gw*EMB + lane*4);
        f.x += nv.x; f.y += nv.y; f.z += nv.z; f.w += nv.w;
        *(float4*)(g_final + (size_t)gw*EMB + lane*4) = f;
    }
}

// ---------------- item_emb = final/3 ; item_n = l2norm ; bf16 ----------------
__global__ void k_item() {
    int gw = (blockIdx.x * blockDim.x + threadIdx.x) >> 5;
    int lane = threadIdx.x & 31;
    if (gw >= N_NODE) return;
    const float inv3 = 1.0f / 3.0f;
    float ss = 0.0f;
    float v[4];
    #pragma unroll
    for (int i = 0; i < 4; ++i) {
        int k = lane + 32*i;
        v[i] = (k < EMB) ? g_final[gw*EMB + k] * inv3 : 0.0f;
        ss += v[i]*v[i];
    }
    ss = warp_sum(ss);
    float invn = 1.0f / fmaxf(sqrtf(ss), EPSN);
    #pragma unroll
    for (int i = 0; i < 4; ++i) {
        int k = lane + 32*i;
        if (k < EMB) {
            float nv = v[i] * invn;
            g_item[gw*EMB + k]  = v[i];
            g_itemn[gw*EMB + k] = nv;
            g_bf16[(size_t)gw*KPAD + k] = __float2bfloat16(nv);
        }
    }
    if (lane < KPAD - EMB) g_bf16[(size_t)gw*KPAD + EMB + lane] = __float2bfloat16(0.0f);
}

// ---------------- session embedding ----------------
__global__ void k_sess(const int* __restrict__ rev, const float* __restrict__ slen,
                       const int* __restrict__ mask, const float* __restrict__ w1,
                       const float* __restrict__ w2, const float* __restrict__ glu1b) {
    __shared__ float sh_seq[SEQ*EMB];
    __shared__ float sh_hs[EMB];
    __shared__ float sh_hsg[EMB];
    __shared__ float sh_nh[EMB];
    __shared__ float sh4[4];
    int b = blockIdx.x, t = threadIdx.x;
    int wid = t >> 5, lane = t & 31;

    for (int idx = t; idx < SEQ*EMB; idx += 128) {
        int l = idx / EMB, k = idx - l*EMB;
        int id = rev[b*SEQ + l];
        sh_seq[idx] = (id == 0) ? 0.0f : g_item[(size_t)(id-1)*EMB + k];
    }
    __syncthreads();
    if (t < EMB) {
        float acc = 0.0f;
        for (int l = 0; l < SEQ; ++l) acc += sh_seq[l*EMB + t];
        sh_hs[t] = acc / slen[b];
    }
    __syncthreads();
    if (t < EMB) {
        float p0=0.f,p1=0.f,p2=0.f,p3=0.f;
        for (int j = 0; j < EMB; j += 4) {
            p0 += sh_hs[j]   * g_glu2T[j*EMB + t];
            p1 += sh_hs[j+1] * g_glu2T[(j+1)*EMB + t];
            p2 += sh_hs[j+2] * g_glu2T[(j+2)*EMB + t];
            p3 += sh_hs[j+3] * g_glu2T[(j+3)*EMB + t];
        }
        sh_hsg[t] = (p0+p1)+(p2+p3);
    }
    __syncthreads();

    float sess_k = 0.0f;
    for (int l = 0; l < SEQ; ++l) {
        if (t < EMB) {
            float p0 = g_posw[l*EMB + t], p1=0.f, p2=0.f, p3=0.f;
            const float* sq = sh_seq + l*EMB;
            for (int j = 0; j < EMB; j += 4) {
                p0 += sq[j]   * w1[(EMB+j)*EMB + t];
                p1 += sq[j+1] * w1[(EMB+j+1)*EMB + t];
                p2 += sq[j+2] * w1[(EMB+j+2)*EMB + t];
                p3 += sq[j+3] * w1[(EMB+j+3)*EMB + t];
            }
            sh_nh[t] = tanhf((p0+p1)+(p2+p3));
        }
        __syncthreads();
        float prod = 0.0f;
        if (t < EMB) {
            float p0 = sh_hsg[t] + glu1b[t], p1=0.f, p2=0.f, p3=0.f;
            for (int j = 0; j < EMB; j += 4) {
                p0 += sh_nh[j]   * g_glu1T[j*EMB + t];
                p1 += sh_nh[j+1] * g_glu1T[(j+1)*EMB + t];
                p2 += sh_nh[j+2] * g_glu1T[(j+2)*EMB + t];
                p3 += sh_nh[j+3] * g_glu1T[(j+3)*EMB + t];
            }
            float g = 1.0f / (1.0f + __expf(-((p0+p1)+(p2+p3))));
            prod = g * w2[t];
        }
        float wsum = warp_sum(prod);
        if (lane == 0) sh4[wid] = wsum;
        __syncthreads();
        float beta = (sh4[0] + sh4[1] + sh4[2] + sh4[3]) * (float)mask[b*SEQ + l];
        if (t < EMB) sess_k += beta * sh_seq[l*EMB + t];
        __syncthreads();
    }
    if (t < EMB) g_sess[b*EMB + t] = sess_k;
}

// ---------------- sess = W_K * l2norm(sess) ----------------
__global__ void k_sess_norm() {
    int gw = (blockIdx.x * blockDim.x + threadIdx.x) >> 5;
    int lane = threadIdx.x & 31;
    if (gw >= BATCH) return;
    float ss = 0.0f;
    float v[4];
    #pragma unroll
    for (int i = 0; i < 4; ++i) {
        int k = lane + 32*i;
        v[i] = (k < EMB) ? g_sess[gw*EMB + k] : 0.0f;
        ss += v[i]*v[i];
    }
    ss = warp_sum(ss);
    float sc = W_KF / fmaxf(sqrtf(ss), EPSN);
    #pragma unroll
    for (int i = 0; i < 4; ++i) {
        int k = lane + 32*i;
        if (k < EMB) g_sessn[gw*EMB + k] = v[i] * sc;
    }
}

// ---------------- scores: 128 items x 64 sessions per block ----------------
#define SC_SMEM ((128*EMB + 64*EMB)*4)
__global__ __launch_bounds__(256) void k_scores(float* __restrict__ scores) {
    extern __shared__ float sm_sc[];
    float* its = sm_sc;
    float* ses = sm_sc + 128*EMB;
    int t = threadIdx.x;
    int nb = blockIdx.x * 128;
    int bb = blockIdx.y * 64;
    for (int i = t; i < 128*EMB; i += 256) {
        int item = nb + i / EMB;
        its[i] = (item < N_NODE) ? g_itemn[(size_t)nb*EMB + i] : 0.0f;
    }
    for (int i = t; i < 64*EMB; i += 256) ses[i] = g_sessn[(size_t)bb*EMB + i];
    __syncthreads();
    int ic = t & 31, sg = t >> 5;
    float acc[8][4];
    #pragma unroll
    for (int j = 0; j < 8; ++j)
        #pragma unroll
        for (int ii = 0; ii < 4; ++ii) acc[j][ii] = 0.0f;
    for (int k4 = 0; k4 < 25; ++k4) {
        float4 iv[4];
        #pragma unroll
        for (int ii = 0; ii < 4; ++ii)
            iv[ii] = *(const float4*)&its[(ic + 32*ii)*EMB + k4*4];
        #pragma unroll
        for (int j = 0; j < 8; ++j) {
            float4 sv = *(const float4*)&ses[(sg*8 + j)*EMB + k4*4];
            #pragma unroll
            for (int ii = 0; ii < 4; ++ii)
                acc[j][ii] += iv[ii].x*sv.x + iv[ii].y*sv.y + iv[ii].z*sv.z + iv[ii].w*sv.w;
        }
    }
    #pragma unroll
    for (int j = 0; j < 8; ++j) {
        int b = bb + sg*8 + j;
        #pragma unroll
        for (int ii = 0; ii < 4; ++ii) {
            int col = nb + ic + 32*ii;
            if (col < N_NODE) scores[(size_t)b * N_NODE + col] = acc[j][ii];
        }
    }
}

// ---------------- loss_item: online CE ----------------
__global__ void k_loss(const float* __restrict__ scores, const int* __restrict__ tar,
                       float* __restrict__ out0) {
    __shared__ float shm[256], shs[256];
    int b = blockIdx.x, t = threadIdx.x;
    const float* row = scores + (size_t)b * N_NODE;
    float m = -INFINITY, s = 0.0f;
    for (int i = t; i < N_NODE; i += 256) {
        float v = row[i];
        if (v > m) { s = s * __expf(m - v) + 1.0f; m = v; }
        else       { s += __expf(v - m); }
    }
    shm[t] = m; shs[t] = s; __syncthreads();
    for (int o = 128; o > 0; o >>= 1) {
        if (t < o) {
            float m2 = shm[t+o], s2 = shs[t+o];
            float M = fmaxf(shm[t], m2);
            shs[t] = shs[t]*__expf(shm[t]-M) + s2*__expf(m2-M);
            shm[t] = M;
        }
        __syncthreads();
    }
    if (t == 0) {
        float lse = shm[0] + logf(shs[0]);
        atomicAdd(out0, (lse - row[tar[b]]) * (1.0f / BATCH));
    }
}

// ---------------- cl GEMM: mma.sync persistent, chain-free grouped top-10 scan ----------------
__global__ __launch_bounds__(128) void k_cl_tc() {
    extern __shared__ __align__(16) char smraw[];   // A 30720 | B0 15360 | B1 15360
    __shared__ int sh_item;
    uint32_t sbase = (uint32_t)__cvta_generic_to_shared(smraw);
    int t = threadIdx.x, lane = t & 31, w = t >> 5;

    for (;;) {
        __syncthreads();
        if (t == 0) sh_item = atomicAdd(&g_work, 1);
        __syncthreads();
        int item = sh_item;
        if (item >= NITEMS) return;
        int rowblk = item >> 4, q = item & 15;
        int rbase = rowblk * CLM;
        int qs = (q * NTILES) / NQ, qe = ((q + 1) * NTILES) / NQ;

        // stage A tile: 128 rows x 112 halves
        const __nv_bfloat16* Ag = g_bf16 + (size_t)rbase * KPAD;
        for (int idx = t; idx < CLM*14; idx += 128) {
            int r = idx / 14, c = idx - r*14;
            *(uint4*)(smraw + (r*BROW + c*8)*2) = *(const uint4*)(Ag + r*KPAD + c*8);
        }
        __syncthreads();

        // A fragments: warp w owns rows w*32..w*32+31; two m16 halves
        uint32_t Af[KC][2][4];
        #pragma unroll
        for (int mh = 0; mh < 2; ++mh) {
            uint32_t aaddr = sbase +
                ((unsigned)(w*32 + mh*16 + (lane & 15))*BROW + ((lane >> 4)*8)) * 2;
            #pragma unroll
            for (int kc = 0; kc < KC; ++kc) {
                asm volatile("ldmatrix.sync.aligned.m8n8.x4.shared.b16 {%0,%1,%2,%3}, [%4];"
                    : "=r"(Af[kc][mh][0]), "=r"(Af[kc][mh][1]),
                      "=r"(Af[kc][mh][2]), "=r"(Af[kc][mh][3])
                    : "r"(aaddr + kc*32));
            }
        }
        __syncthreads();

        // prologue: async-load first B tile
        {
            const __nv_bfloat16* Bg = g_bf16 + (size_t)qs * CLN * KPAD;
            uint32_t dst = sbase + A_BYTES + (uint32_t)(qs & 1) * B_BYTES;
            for (int idx = t; idx < CLN*14; idx += 128) {
                int r = idx / 14, c = idx - r*14;
                uint32_t d = dst + (unsigned)(r*BROW + c*8)*2;
                const void* s = Bg + r*KPAD + c*8;
                asm volatile("cp.async.cg.shared.global [%0], [%1], 16;" :: "r"(d), "l"(s));
            }
            asm volatile("cp.async.commit_group;" ::: "memory");
        }

        // 4 top-10 lists (raw units): rows w*32 + mh*16 + (lane>>2) + half*8
        float tk0[TOPK], tk1[TOPK], tk2[TOPK], tk3[TOPK];
        float thr0 = -INFINITY, thr1 = -INFINITY, thr2 = -INFINITY, thr3 = -INFINITY;
        #pragma unroll
        for (int i = 0; i < TOPK; ++i) {
            tk0[i] = -INFINITY; tk1[i] = -INFINITY;
            tk2[i] = -INFINITY; tk3[i] = -INFINITY;
        }

        int quad = lane >> 3, r8 = lane & 7;
        uint32_t bth = ((unsigned)(r8 + 8*(quad >> 1))*BROW + (quad & 1)*8) * 2;

        for (int tile = qs; tile < qe; ++tile) {
            asm volatile("cp.async.wait_group 0;" ::: "memory");
            __syncthreads();
            if (tile + 1 < qe) {
                const __nv_bfloat16* Bg = g_bf16 + (size_t)(tile + 1) * CLN * KPAD;
                uint32_t dst = sbase + A_BYTES + (uint32_t)((tile + 1) & 1) * B_BYTES;
                for (int idx = t; idx < CLN*14; idx += 128) {
                    int r = idx / 14, c = idx - r*14;
                    uint32_t d = dst + (unsigned)(r*BROW + c*8)*2;
                    const void* s = Bg + r*KPAD + c*8;
                    asm volatile("cp.async.cg.shared.global [%0], [%1], 16;" :: "r"(d), "l"(s));
                }
                asm volatile("cp.async.commit_group;" ::: "memory");
            }
            uint32_t bb = sbase + A_BYTES + (uint32_t)(tile & 1)*B_BYTES + bth;
            int npairs = (tile == NTILES-1) ? 2 : 4;
            for (int p = 0; p < npairs; ++p) {
                uint32_t ba = bb + (unsigned)p*(16*BROW*2);
                uint32_t Bf[KC][4];
                #pragma unroll
                for (int kc = 0; kc < KC; ++kc) {
                    asm volatile("ldmatrix.sync.aligned.m8n8.x4.shared.b16 {%0,%1,%2,%3}, [%4];"
                        : "=r"(Bf[kc][0]), "=r"(Bf[kc][1]), "=r"(Bf[kc][2]), "=r"(Bf[kc][3])
                        : "r"(ba + kc*32));
                }
                #pragma unroll
                for (int mh = 0; mh < 2; ++mh) {
                    float d0[4] = {0.f,0.f,0.f,0.f}, d1[4] = {0.f,0.f,0.f,0.f};
                    #pragma unroll
                    for (int kc = 0; kc < KC; ++kc) {
                        asm volatile("mma.sync.aligned.m16n8k16.row.col.f32.bf16.bf16.f32 "
                            "{%0,%1,%2,%3}, {%4,%5,%6,%7}, {%8,%9}, {%0,%1,%2,%3};"
                            : "+f"(d0[0]), "+f"(d0[1]), "+f"(d0[2]), "+f"(d0[3])
                            : "r"(Af[kc][mh][0]), "r"(Af[kc][mh][1]),
                              "r"(Af[kc][mh][2]), "r"(Af[kc][mh][3]),
                              "r"(Bf[kc][0]), "r"(Bf[kc][1]));
                        asm volatile("mma.sync.aligned.m16n8k16.row.col.f32.bf16.bf16.f32 "
                            "{%0,%1,%2,%3}, {%4,%5,%6,%7}, {%8,%9}, {%0,%1,%2,%3};"
                            : "+f"(d1[0]), "+f"(d1[1]), "+f"(d1[2]), "+f"(d1[3])
                            : "r"(Af[kc][mh][0]), "r"(Af[kc][mh][1]),
                              "r"(Af[kc][mh][2]), "r"(Af[kc][mh][3]),
                              "r"(Bf[kc][2]), "r"(Bf[kc][3]));
                    }
                    if (mh == 0) {
                        scan4(tk0, thr0, d0[0], d0[1], d1[0], d1[1]);
                        scan4(tk1, thr1, d0[2], d0[3], d1[2], d1[3]);
                    } else {
                        scan4(tk2, thr2, d0[0], d0[1], d1[0], d1[1]);
                        scan4(tk3, thr3, d0[2], d0[3], d1[2], d1[3]);
                    }
                }
            }
        }

        // merge: 4 thread-local lists per row (lane&3) via smem [128][40]
        __syncthreads();
        float* mg = (float*)smraw;
        int g = lane >> 2, i4 = lane & 3;
        int base_r = w*32 + g;
        #pragma unroll
        for (int qq = 0; qq < TOPK; ++qq) {
            mg[(base_r     )*40 + i4*TOPK + qq] = tk0[qq];
            mg[(base_r + 8 )*40 + i4*TOPK + qq] = tk1[qq];
            mg[(base_r + 16)*40 + i4*TOPK + qq] = tk2[qq];
            mg[(base_r + 24)*40 + i4*TOPK + qq] = tk3[qq];
        }
        __syncthreads();
        {
            int row = rbase + t;
            if (row < N_NODE) {
                float m[TOPK];
                #pragma unroll
                for (int qq = 0; qq < TOPK; ++qq) m[qq] = -INFINITY;
                for (int qq = 0; qq < 4*TOPK; ++qq) topk_insert(m, mg[t*40 + qq]);
                #pragma unroll
                for (int qq = 0; qq < TOPK; ++qq)
                    g_qtk[((size_t)row*NQ + q)*TOPK + qq] = m[qq] * INV_TEMP;
            }
        }
    }
}

// ---------------- cl merge ----------------
__global__ void k_cl_merge(float* __restrict__ out_cl) {
    __shared__ float sh[256];
    int idx = blockIdx.x * 256 + threadIdx.x;
    float contrib = 0.0f;
    if (idx < N_NODE) {
        float m[TOPK];
        #pragma unroll
        for (int q = 0; q < TOPK; ++q) m[q] = -INFINITY;
        const float* p = g_qtk + (size_t)idx*NQ*TOPK;
        for (int q = 0; q < NQ*TOPK; ++q) topk_insert(m, p[q]);
        float se = 0.0f;
        #pragma unroll
        for (int q = 1; q < TOPK; ++q) se += __expf(m[q] - m[0]);
        contrib = log1pf(se) * (CL_WF / (float)N_NODE);
    }
    sh[threadIdx.x] = contrib; __syncthreads();
    for (int s = 128; s > 0; s >>= 1) {
        if (threadIdx.x < s) sh[threadIdx.x] += sh[threadIdx.x + s];
        __syncthreads();
    }
    if (threadIdx.x == 0) atomicAdd(out_cl, sh[0]);
}

// ---------------- launch ----------------
extern "C" void kernel_launch(void* const* d_in, const int* in_sizes, int n_in,
                              void* d_out, int out_size) {
    const float* slen  = (const float*)d_in[1];
    const int*   rev   = (const int*)d_in[2];
    const int*   mask  = (const int*)d_in[3];
    const int*   tar   = (const int*)d_in[5];
    const int*   arow  = (const int*)d_in[8];
    const int*   acol  = (const int*)d_in[9];
    const float* avals = (const float*)d_in[10];
    const float* emb   = (const float*)d_in[11];
    const float* pos   = (const float*)d_in[12];
    const float* witem = (const float*)d_in[13];
    const float* attw  = (const float*)d_in[14];
    const float* attb  = (const float*)d_in[15];
    const float* w1    = (const float*)d_in[16];
    const float* w2    = (const float*)d_in[17];
    const float* glu1  = (const float*)d_in[18];
    const float* glu1b = (const float*)d_in[19];
    const float* glu2  = (const float*)d_in[20];
    float* out = (float*)d_out;
    int E = in_sizes[8];

    cudaFuncSetAttribute(k_cl_tc, cudaFuncAttributeMaxDynamicSharedMemorySize, CL_SMEM);
    cudaFuncSetAttribute(k_scores, cudaFuncAttributeMaxDynamicSharedMemorySize, SC_SMEM);
    cudaFuncSetAttribute(k_lin_att, cudaFuncAttributeMaxDynamicSharedMemorySize,
                         (EMB*EMB + 64*EMB)*4);

    k_init<<<2048, 256>>>(emb, out, out_size);
    k_transpose<<<(N_LAYERS*EMB*EMB + 255)/256, 256>>>(witem, glu1, glu2);
    k_posw<<<SEQ, 128>>>(pos, w1);
    k_prep<<<(E + 255)/256, 256>>>(arow, acol, avals, E);
    k_scan<<<1, 1024>>>();
    k_scatter<<<(E + 255)/256, 256>>>(arow, acol, avals, E);

    for (int l = 0; l < N_LAYERS; ++l) {
        k_att_score<<<(N_NODE*32 + 255)/256, 256>>>(attw, attb);
        k_softmax_reduce<<<1, 1024>>>();
        k_lin_att<<<(N_NODE + 63)/64, 256, (EMB*EMB + 64*EMB)*4>>>(l);
        k_spmm_csr<<<(N_NODE*32 + 255)/256, 256>>>();
    }

    k_item<<<(N_NODE*32 + 255)/256, 256>>>();
    k_sess<<<BATCH, 128>>>(rev, slen, mask, w1, w2, glu1b);
    k_sess_norm<<<(BATCH*32 + 255)/256, 256>>>();

    dim3 sg((N_NODE + 127)/128, BATCH/64);
    k_scores<<<sg, 256, SC_SMEM>>>(out + 1);

    k_loss<<<BATCH, 256>>>(out + 1, tar, out);
    k_cl_tc<<<CLGRID, 128, CL_SMEM>>>();
    k_cl_merge<<<(N_NODE + 255)/256, 256>>>(out + out_size - 1);
}

// round 12
// speedup vs baseline: 1.3249x; 1.3249x over previous
#include <cuda_runtime.h>
#include <cuda_bf16.h>
#include <math.h>
#include <stdint.h>

#define N_NODE 20000
#define EMB 100
#define BATCH 512
#define SEQ 50
#define N_LAYERS 2
#define INV_TEMP 10.0f
#define W_KF 10.0f
#define TOPK 10
#define CL_WF 100.0f
#define EPSN 1e-12f
#define EMAX 345000
#define NROWS_S (BATCH*SEQ)     // 25600

// mma.sync cl gemm tiling
#define KPAD 112                // K padded to 7*16
#define KC 7
#define CLM 128                 // rows per CTA
#define CLN 64                  // cols per tile
#define NBLK 157                // ceil(20000/128)
#define ROWS_PAD (NBLK*CLM)     // 20096
#define NTILES 313              // ceil(20000/64)
#define BROW 120                // smem row stride in halves (240B)
#define NQ 8
#define NITEMS (NBLK*NQ)        // 1256
#define CLGRID 296
#define A_BYTES (CLM*BROW*2)    // 30720
#define B_BYTES (CLN*BROW*2)    // 15360
#define CL_SMEM (A_BYTES + 2*B_BYTES)  // 61440

// ---------------- scratch ----------------
__device__ float g_colsum[N_NODE];
__device__ int   g_cnt[N_NODE];
__device__ int   g_rowptr[N_NODE+1];
__device__ int   g_cursor[N_NODE];
__device__ int   g_ecol[EMAX];
__device__ float g_eval[EMAX];
__device__ int   g_work;
__device__ float g_x[N_NODE*EMB];
__device__ float g_y[N_NODE*EMB];
__device__ float g_final[N_NODE*EMB];
__device__ float g_item[N_NODE*EMB];
__device__ float g_itemn[N_NODE*EMB];
__device__ float g_s[N_NODE];
__device__ float g_amax;
__device__ float g_asum;
__device__ float g_wT[N_LAYERS*EMB*EMB];
__device__ float g_glu1T[EMB*EMB];
__device__ float g_glu2T[EMB*EMB];
__device__ float g_sess[BATCH*EMB];
__device__ float g_sessn[BATCH*EMB];
__device__ float g_posw[SEQ*EMB];
__device__ float g_seqh[(size_t)NROWS_S*EMB];   // 10.24 MB
__device__ float g_nh[(size_t)NROWS_S*EMB];     // 10.24 MB
__device__ float g_hsg[BATCH*EMB];
__device__ float g_beta[NROWS_S];
__device__ float g_qtk[(size_t)ROWS_PAD*NQ*TOPK];
__device__ __align__(16) __nv_bfloat16 g_bf16[(size_t)ROWS_PAD*KPAD];

// ---------------- helpers ----------------
__device__ __forceinline__ float warp_sum(float v) {
    #pragma unroll
    for (int o = 16; o > 0; o >>= 1) v += __shfl_xor_sync(0xffffffffu, v, o);
    return v;
}

__device__ __forceinline__ void topk_insert(float (&tk)[TOPK], float v) {
    if (v > tk[TOPK-1]) {
        tk[TOPK-1] = v;
        #pragma unroll
        for (int i = TOPK-1; i > 0; --i) {
            if (tk[i] > tk[i-1]) { float tmp = tk[i-1]; tk[i-1] = tk[i]; tk[i] = tmp; }
        }
    }
}

// ---------------- init ----------------
__global__ void k_init(const float* __restrict__ emb, float* __restrict__ out, int out_size) {
    int stride = gridDim.x * blockDim.x;
    int i0 = blockIdx.x * blockDim.x + threadIdx.x;
    for (int i = i0; i < N_NODE*EMB; i += stride) {
        float v = emb[i];
        g_x[i] = v;
        g_final[i] = v;
        if (i < N_NODE) { g_colsum[i] = 0.0f; g_cnt[i] = 0; }
    }
    for (int i = i0; i < (ROWS_PAD - N_NODE)*KPAD; i += stride)
        g_bf16[(size_t)N_NODE*KPAD + i] = __float2bfloat16(0.0f);
    if (i0 == 0) { out[0] = 0.0f; out[out_size-1] = 0.0f; g_work = 0; }
}

// ---------------- transpose weights ----------------
__global__ void k_transpose(const float* __restrict__ w_item,
                            const float* __restrict__ glu1,
                            const float* __restrict__ glu2) {
    int i = blockIdx.x * blockDim.x + threadIdx.x;
    if (i < N_LAYERS*EMB*EMB) {
        int l = i / (EMB*EMB);
        int r = i - l*(EMB*EMB);
        int j = r / EMB, k = r - j*EMB;
        g_wT[l*EMB*EMB + j*EMB + k] = w_item[l*EMB*EMB + k*EMB + j];
    }
    if (i < EMB*EMB) {
        int j = i / EMB, k = i - j*EMB;
        g_glu1T[j*EMB + k] = glu1[k*EMB + j];
        g_glu2T[j*EMB + k] = glu2[k*EMB + j];
    }
}

// ---------------- posW ----------------
__global__ void k_posw(const float* __restrict__ pos, const float* __restrict__ w1) {
    int l = blockIdx.x, t = threadIdx.x;
    if (t < EMB) {
        float acc = 0.0f;
        for (int j = 0; j < EMB; ++j) acc += pos[l*EMB + j] * w1[j*EMB + t];
        g_posw[l*EMB + t] = acc;
    }
}

// ---------------- edge pass: column sums + row degrees ----------------
__global__ void k_prep(const int* __restrict__ row, const int* __restrict__ col,
                       const float* __restrict__ vals, int E) {
    int e = blockIdx.x * blockDim.x + threadIdx.x;
    if (e < E) {
        atomicAdd(&g_colsum[col[e]], vals[e]);
        atomicAdd(&g_cnt[row[e]], 1);
    }
}

// ---------------- prefix sum -> rowptr ----------------
__global__ void k_scan() {
    __shared__ int sh[1024];
    int t = threadIdx.x;
    const int CH = 20;
    int local[CH];
    int s = 0;
    #pragma unroll
    for (int i = 0; i < CH; ++i) {
        int idx = t*CH + i;
        int c = (idx < N_NODE) ? g_cnt[idx] : 0;
        local[i] = s; s += c;
    }
    sh[t] = s; __syncthreads();
    for (int off = 1; off < 1024; off <<= 1) {
        int v = (t >= off) ? sh[t-off] : 0;
        __syncthreads();
        if (t >= off) sh[t] += v;
        __syncthreads();
    }
    int base = (t == 0) ? 0 : sh[t-1];
    #pragma unroll
    for (int i = 0; i < CH; ++i) {
        int idx = t*CH + i;
        if (idx < N_NODE) {
            int p = base + local[i];
            g_rowptr[idx] = p;
            g_cursor[idx] = p;
        }
    }
    if (t == 1023) g_rowptr[N_NODE] = sh[1023];
}

// ---------------- scatter edges into CSR ----------------
__global__ void k_scatter(const int* __restrict__ row, const int* __restrict__ col,
                          const float* __restrict__ vals, int E) {
    int e = blockIdx.x * blockDim.x + threadIdx.x;
    if (e >= E) return;
    int c = col[e], r = row[e];
    float v = vals[e] / g_colsum[c];
    int p = atomicAdd(&g_cursor[r], 1);
    g_ecol[p] = c;
    g_eval[p] = v;
}

// ---------------- attention scores ----------------
__global__ void k_att_score(const float* __restrict__ attw, const float* __restrict__ attb) {
    int gw = (blockIdx.x * blockDim.x + threadIdx.x) >> 5;
    int lane = threadIdx.x & 31;
    if (gw >= N_NODE) return;
    const float* xr = g_x + gw*EMB;
    float acc = 0.0f;
    for (int k = lane; k < EMB; k += 32) acc += xr[k] * attw[k];
    acc = warp_sum(acc);
    if (lane == 0) g_s[gw] = acc + attb[0];
}

// ---------------- softmax reduce ----------------
__global__ void k_softmax_reduce() {
    __shared__ float sh[1024];
    int t = threadIdx.x;
    float m = -INFINITY;
    for (int i = t; i < N_NODE; i += 1024) m = fmaxf(m, g_s[i]);
    sh[t] = m; __syncthreads();
    for (int s = 512; s > 0; s >>= 1) { if (t < s) sh[t] = fmaxf(sh[t], sh[t+s]); __syncthreads(); }
    float mx = sh[0]; __syncthreads();
    float sum = 0.0f;
    for (int i = t; i < N_NODE; i += 1024) sum += __expf(g_s[i] - mx);
    sh[t] = sum; __syncthreads();
    for (int s = 512; s > 0; s >>= 1) { if (t < s) sh[t] += sh[t+s]; __syncthreads(); }
    if (t == 0) { g_amax = mx; g_asum = sh[0]; }
}

// ---------------- y = (x @ W^T) * att  (WT staged in smem) ----------------
__global__ void k_lin_att(int layer) {
    extern __shared__ float sm_la[];
    float* WT = sm_la;            // [100][100]
    float* xs = sm_la + EMB*EMB;  // [64][100]
    int base = blockIdx.x * 64;
    int t = threadIdx.x;
    int nvalid = min(64, N_NODE - base);
    const float* WTg = g_wT + layer*EMB*EMB;
    for (int i = t; i < EMB*EMB; i += 256) WT[i] = WTg[i];
    for (int i = t; i < nvalid*EMB; i += 256) xs[i] = g_x[base*EMB + i];
    __syncthreads();
    float inv = 1.0f / g_asum;
    float mx  = g_amax;
    int npairs = nvalid * 25;
    for (int p = t; p < npairs; p += 256) {
        int n = p / 25, k4 = p - n*25;
        float a0 = 0.f, a1 = 0.f, a2 = 0.f, a3 = 0.f;
        const float* xr = xs + n*EMB;
        #pragma unroll 4
        for (int j = 0; j < EMB; ++j) {
            float xv = xr[j];
            float4 wv = *(const float4*)&WT[j*EMB + k4*4];
            a0 += xv*wv.x; a1 += xv*wv.y; a2 += xv*wv.z; a3 += xv*wv.w;
        }
        float att = __expf(g_s[base + n] - mx) * inv;
        float4 o = make_float4(a0*att, a1*att, a2*att, a3*att);
        *(float4*)(g_y + (size_t)(base + n)*EMB + k4*4) = o;
    }
}

// ---------------- CSR SpMM fused with l2norm + final accumulate ----------------
__global__ void k_spmm_csr() {
    int gw = (blockIdx.x * blockDim.x + threadIdx.x) >> 5;
    int lane = threadIdx.x & 31;
    if (gw >= N_NODE) return;
    int s = g_rowptr[gw], e = g_rowptr[gw+1];
    bool act = lane < 25;
    float4 acc = make_float4(0.f, 0.f, 0.f, 0.f);
    for (int i = s; i < e; ++i) {
        int c = g_ecol[i];
        float v = g_eval[i];
        if (act) {
            float4 yv = *(const float4*)(g_y + (size_t)c*EMB + lane*4);
            acc.x += v*yv.x; acc.y += v*yv.y; acc.z += v*yv.z; acc.w += v*yv.w;
        }
    }
    float ss = acc.x*acc.x + acc.y*acc.y + acc.z*acc.z + acc.w*acc.w;
    ss = warp_sum(ss);
    float invn = 1.0f / fmaxf(sqrtf(ss), EPSN);
    if (act) {
        float4 nv = make_float4(acc.x*invn, acc.y*invn, acc.z*invn, acc.w*invn);
        *(float4*)(g_x + (size_t)gw*EMB + lane*4) = nv;
        float4 f = *(const float4*)(g_final + (size_t)gw*EMB + lane*4);
        f.x += nv.x; f.y += nv.y; f.z += nv.z; f.w += nv.w;
        *(float4*)(g_final + (size_t)gw*EMB + lane*4) = f;
    }
}

// ---------------- item_emb = final/3 ; item_n = l2norm ; bf16 ----------------
__global__ void k_item() {
    int gw = (blockIdx.x * blockDim.x + threadIdx.x) >> 5;
    int lane = threadIdx.x & 31;
    if (gw >= N_NODE) return;
    const float inv3 = 1.0f / 3.0f;
    float ss = 0.0f;
    float v[4];
    #pragma unroll
    for (int i = 0; i < 4; ++i) {
        int k = lane + 32*i;
        v[i] = (k < EMB) ? g_final[gw*EMB + k] * inv3 : 0.0f;
        ss += v[i]*v[i];
    }
    ss = warp_sum(ss);
    float invn = 1.0f / fmaxf(sqrtf(ss), EPSN);
    #pragma unroll
    for (int i = 0; i < 4; ++i) {
        int k = lane + 32*i;
        if (k < EMB) {
            float nv = v[i] * invn;
            g_item[gw*EMB + k]  = v[i];
            g_itemn[gw*EMB + k] = nv;
            g_bf16[(size_t)gw*KPAD + k] = __float2bfloat16(nv);
        }
    }
    if (lane < KPAD - EMB) g_bf16[(size_t)gw*KPAD + EMB + lane] = __float2bfloat16(0.0f);
}

// ---------------- sess stage 1: gather seq_h, compute hs -> hsg ----------------
__global__ void k_sess_pre(const int* __restrict__ rev, const float* __restrict__ slen) {
    __shared__ float sh_seq[SEQ*EMB];
    __shared__ float sh_hs[EMB];
    int b = blockIdx.x, t = threadIdx.x;
    for (int idx = t; idx < SEQ*EMB; idx += 128) {
        int l = idx / EMB, k = idx - l*EMB;
        int id = rev[b*SEQ + l];
        float v = (id == 0) ? 0.0f : g_item[(size_t)(id-1)*EMB + k];
        sh_seq[idx] = v;
        g_seqh[(size_t)b*SEQ*EMB + idx] = v;
    }
    __syncthreads();
    if (t < EMB) {
        float acc = 0.0f;
        for (int l = 0; l < SEQ; ++l) acc += sh_seq[l*EMB + t];
        sh_hs[t] = acc / slen[b];
    }
    __syncthreads();
    if (t < EMB) {
        float p0=0.f,p1=0.f,p2=0.f,p3=0.f;
        for (int j = 0; j < EMB; j += 4) {
            p0 += sh_hs[j]   * g_glu2T[j*EMB + t];
            p1 += sh_hs[j+1] * g_glu2T[(j+1)*EMB + t];
            p2 += sh_hs[j+2] * g_glu2T[(j+2)*EMB + t];
            p3 += sh_hs[j+3] * g_glu2T[(j+3)*EMB + t];
        }
        g_hsg[b*EMB + t] = (p0+p1)+(p2+p3);
    }
}

// ---------------- sess stage 2: nh = tanh(posw[l] + seq_h @ w1half)  (batched GEMM) ----------------
#define NH_SMEM ((EMB*EMB + 64*EMB)*4)
__global__ __launch_bounds__(256) void k_nh(const float* __restrict__ w1h) {
    extern __shared__ float sm_nh[];
    float* W  = sm_nh;            // [100][100]
    float* xs = sm_nh + EMB*EMB;  // [64][100]
    int base = blockIdx.x * 64;   // 25600/64 = 400 blocks, exact
    int t = threadIdx.x;
    for (int i = t; i < EMB*EMB; i += 256) W[i] = w1h[i];
    for (int i = t; i < 64*EMB; i += 256) xs[i] = g_seqh[(size_t)base*EMB + i];
    __syncthreads();
    for (int p = t; p < 64*25; p += 256) {
        int n = p / 25, k4 = p - n*25;
        float a0 = 0.f, a1 = 0.f, a2 = 0.f, a3 = 0.f;
        const float* xr = xs + n*EMB;
        #pragma unroll 4
        for (int j = 0; j < EMB; ++j) {
            float xv = xr[j];
            float4 wv = *(const float4*)&W[j*EMB + k4*4];
            a0 += xv*wv.x; a1 += xv*wv.y; a2 += xv*wv.z; a3 += xv*wv.w;
        }
        int r = base + n;
        int l = r - (r / SEQ) * SEQ;
        float4 pw = *(const float4*)&g_posw[l*EMB + k4*4];
        float4 o = make_float4(tanhf(pw.x + a0), tanhf(pw.y + a1),
                               tanhf(pw.z + a2), tanhf(pw.w + a3));
        *(float4*)(g_nh + (size_t)r*EMB + k4*4) = o;
    }
}

// ---------------- sess stage 3: gate = sigmoid(nh @ glu1T + glu1b + hsg); beta = gate.w2 ----------------
#define NB_SMEM ((EMB*EMB + 64*EMB + 64)*4)
__global__ __launch_bounds__(256) void k_beta(const int* __restrict__ mask,
                                              const float* __restrict__ w2,
                                              const float* __restrict__ glu1b) {
    extern __shared__ float sm_nb[];
    float* G  = sm_nb;                 // [100][100]
    float* xs = sm_nb + EMB*EMB;       // [64][100]
    float* sb = sm_nb + EMB*EMB + 64*EMB;  // [64]
    int base = blockIdx.x * 64;
    int t = threadIdx.x;
    for (int i = t; i < EMB*EMB; i += 256) G[i] = g_glu1T[i];
    for (int i = t; i < 64*EMB; i += 256) xs[i] = g_nh[(size_t)base*EMB + i];
    if (t < 64) sb[t] = 0.0f;
    __syncthreads();
    for (int p = t; p < 64*25; p += 256) {
        int n = p / 25, k4 = p - n*25;
        float a0 = 0.f, a1 = 0.f, a2 = 0.f, a3 = 0.f;
        const float* xr = xs + n*EMB;
        #pragma unroll 4
        for (int j = 0; j < EMB; ++j) {
            float xv = xr[j];
            float4 gv = *(const float4*)&G[j*EMB + k4*4];
            a0 += xv*gv.x; a1 += xv*gv.y; a2 += xv*gv.z; a3 += xv*gv.w;
        }
        int r = base + n;
        int b = r / SEQ;
        float4 hb = *(const float4*)&g_hsg[b*EMB + k4*4];
        float4 bb = *(const float4*)&glu1b[k4*4];
        float4 wv = *(const float4*)&w2[k4*4];
        float c = 0.0f;
        c += wv.x / (1.0f + __expf(-(a0 + bb.x + hb.x)));
        c += wv.y / (1.0f + __expf(-(a1 + bb.y + hb.y)));
        c += wv.z / (1.0f + __expf(-(a2 + bb.z + hb.z)));
        c += wv.w / (1.0f + __expf(-(a3 + bb.w + hb.w)));
        atomicAdd(&sb[n], c);
    }
    __syncthreads();
    if (t < 64) {
        int r = base + t;
        int b = r / SEQ, l = r - b*SEQ;
        g_beta[r] = sb[t] * (float)mask[b*SEQ + l];
    }
}

// ---------------- sess stage 4: sess[b] = sum_l beta * seq_h ----------------
__global__ void k_sessagg() {
    __shared__ float bet[SEQ];
    int b = blockIdx.x, t = threadIdx.x;
    if (t < SEQ) bet[t] = g_beta[b*SEQ + t];
    __syncthreads();
    if (t < EMB) {
        float s = 0.0f;
        const float* sq = g_seqh + (size_t)b*SEQ*EMB + t;
        #pragma unroll 5
        for (int l = 0; l < SEQ; ++l) s += bet[l] * sq[l*EMB];
        g_sess[b*EMB + t] = s;
    }
}

// ---------------- sess = W_K * l2norm(sess) ----------------
__global__ void k_sess_norm() {
    int gw = (blockIdx.x * blockDim.x + threadIdx.x) >> 5;
    int lane = threadIdx.x & 31;
    if (gw >= BATCH) return;
    float ss = 0.0f;
    float v[4];
    #pragma unroll
    for (int i = 0; i < 4; ++i) {
        int k = lane + 32*i;
        v[i] = (k < EMB) ? g_sess[gw*EMB + k] : 0.0f;
        ss += v[i]*v[i];
    }
    ss = warp_sum(ss);
    float sc = W_KF / fmaxf(sqrtf(ss), EPSN);
    #pragma unroll
    for (int i = 0; i < 4; ++i) {
        int k = lane + 32*i;
        if (k < EMB) g_sessn[gw*EMB + k] = v[i] * sc;
    }
}

// ---------------- scores: 128 items x 64 sessions per block ----------------
#define SC_SMEM ((128*EMB + 64*EMB)*4)
__global__ __launch_bounds__(256) void k_scores(float* __restrict__ scores) {
    extern __shared__ float sm_sc[];
    float* its = sm_sc;
    float* ses = sm_sc + 128*EMB;
    int t = threadIdx.x;
    int nb = blockIdx.x * 128;
    int bb = blockIdx.y * 64;
    for (int i = t; i < 128*EMB; i += 256) {
        int item = nb + i / EMB;
        its[i] = (item < N_NODE) ? g_itemn[(size_t)nb*EMB + i] : 0.0f;
    }
    for (int i = t; i < 64*EMB; i += 256) ses[i] = g_sessn[(size_t)bb*EMB + i];
    __syncthreads();
    int ic = t & 31, sg = t >> 5;
    float acc[8][4];
    #pragma unroll
    for (int j = 0; j < 8; ++j)
        #pragma unroll
        for (int ii = 0; ii < 4; ++ii) acc[j][ii] = 0.0f;
    for (int k4 = 0; k4 < 25; ++k4) {
        float4 iv[4];
        #pragma unroll
        for (int ii = 0; ii < 4; ++ii)
            iv[ii] = *(const float4*)&its[(ic + 32*ii)*EMB + k4*4];
        #pragma unroll
        for (int j = 0; j < 8; ++j) {
            float4 sv = *(const float4*)&ses[(sg*8 + j)*EMB + k4*4];
            #pragma unroll
            for (int ii = 0; ii < 4; ++ii)
                acc[j][ii] += iv[ii].x*sv.x + iv[ii].y*sv.y + iv[ii].z*sv.z + iv[ii].w*sv.w;
        }
    }
    #pragma unroll
    for (int j = 0; j < 8; ++j) {
        int b = bb + sg*8 + j;
        #pragma unroll
        for (int ii = 0; ii < 4; ++ii) {
            int col = nb + ic + 32*ii;
            if (col < N_NODE) scores[(size_t)b * N_NODE + col] = acc[j][ii];
        }
    }
}

// ---------------- loss_item: online CE ----------------
__global__ void k_loss(const float* __restrict__ scores, const int* __restrict__ tar,
                       float* __restrict__ out0) {
    __shared__ float shm[256], shs[256];
    int b = blockIdx.x, t = threadIdx.x;
    const float* row = scores + (size_t)b * N_NODE;
    float m = -INFINITY, s = 0.0f;
    for (int i = t; i < N_NODE; i += 256) {
        float v = row[i];
        if (v > m) { s = s * __expf(m - v) + 1.0f; m = v; }
        else       { s += __expf(v - m); }
    }
    shm[t] = m; shs[t] = s; __syncthreads();
    for (int o = 128; o > 0; o >>= 1) {
        if (t < o) {
            float m2 = shm[t+o], s2 = shs[t+o];
            float M = fmaxf(shm[t], m2);
            shs[t] = shs[t]*__expf(shm[t]-M) + s2*__expf(m2-M);
            shm[t] = M;
        }
        __syncthreads();
    }
    if (t == 0) {
        float lse = shm[0] + logf(shs[0]);
        atomicAdd(out0, (lse - row[tar[b]]) * (1.0f / BATCH));
    }
}

// ---------------- cl GEMM: mma.sync persistent (R7 config), fused top-10 ----------------
__global__ __launch_bounds__(128) void k_cl_tc() {
    extern __shared__ __align__(16) char smraw[];   // A 30720 | B0 15360 | B1 15360
    __shared__ int sh_item;
    uint32_t sbase = (uint32_t)__cvta_generic_to_shared(smraw);
    int t = threadIdx.x, lane = t & 31, w = t >> 5;

    for (;;) {
        __syncthreads();
        if (t == 0) sh_item = atomicAdd(&g_work, 1);
        __syncthreads();
        int item = sh_item;
        if (item >= NITEMS) return;
        int rowblk = item >> 3, q = item & 7;
        int rbase = rowblk * CLM;
        int qs = (q * NTILES) / NQ, qe = ((q + 1) * NTILES) / NQ;

        // stage A tile: 128 rows x 112 halves
        const __nv_bfloat16* Ag = g_bf16 + (size_t)rbase * KPAD;
        for (int idx = t; idx < CLM*14; idx += 128) {
            int r = idx / 14, c = idx - r*14;
            *(uint4*)(smraw + (r*BROW + c*8)*2) = *(const uint4*)(Ag + r*KPAD + c*8);
        }
        __syncthreads();

        // A fragments: warp w owns rows w*32..w*32+31; two m16 halves
        uint32_t Af[KC][2][4];
        #pragma unroll
        for (int mh = 0; mh < 2; ++mh) {
            uint32_t aaddr = sbase +
                ((unsigned)(w*32 + mh*16 + (lane & 15))*BROW + ((lane >> 4)*8)) * 2;
            #pragma unroll
            for (int kc = 0; kc < KC; ++kc) {
                asm volatile("ldmatrix.sync.aligned.m8n8.x4.shared.b16 {%0,%1,%2,%3}, [%4];"
                    : "=r"(Af[kc][mh][0]), "=r"(Af[kc][mh][1]),
                      "=r"(Af[kc][mh][2]), "=r"(Af[kc][mh][3])
                    : "r"(aaddr + kc*32));
            }
        }
        __syncthreads();

        // prologue: async-load first B tile
        {
            const __nv_bfloat16* Bg = g_bf16 + (size_t)qs * CLN * KPAD;
            uint32_t dst = sbase + A_BYTES + (uint32_t)(qs & 1) * B_BYTES;
            for (int idx = t; idx < CLN*14; idx += 128) {
                int r = idx / 14, c = idx - r*14;
                uint32_t d = dst + (unsigned)(r*BROW + c*8)*2;
                const void* s = Bg + r*KPAD + c*8;
                asm volatile("cp.async.cg.shared.global [%0], [%1], 16;" :: "r"(d), "l"(s));
            }
            asm volatile("cp.async.commit_group;" ::: "memory");
        }

        // 4 top-10 lists (raw units)
        float tk0[TOPK], tk1[TOPK], tk2[TOPK], tk3[TOPK];
        #pragma unroll
        for (int i = 0; i < TOPK; ++i) {
            tk0[i] = -INFINITY; tk1[i] = -INFINITY;
            tk2[i] = -INFINITY; tk3[i] = -INFINITY;
        }

        int quad = lane >> 3, r8 = lane & 7;
        uint32_t bth = ((unsigned)(r8 + 8*(quad >> 1))*BROW + (quad & 1)*8) * 2;

        for (int tile = qs; tile < qe; ++tile) {
            asm volatile("cp.async.wait_group 0;" ::: "memory");
            __syncthreads();
            if (tile + 1 < qe) {
                const __nv_bfloat16* Bg = g_bf16 + (size_t)(tile + 1) * CLN * KPAD;
                uint32_t dst = sbase + A_BYTES + (uint32_t)((tile + 1) & 1) * B_BYTES;
                for (int idx = t; idx < CLN*14; idx += 128) {
                    int r = idx / 14, c = idx - r*14;
                    uint32_t d = dst + (unsigned)(r*BROW + c*8)*2;
                    const void* s = Bg + r*KPAD + c*8;
                    asm volatile("cp.async.cg.shared.global [%0], [%1], 16;" :: "r"(d), "l"(s));
                }
                asm volatile("cp.async.commit_group;" ::: "memory");
            }
            uint32_t bb = sbase + A_BYTES + (uint32_t)(tile & 1)*B_BYTES + bth;
            int npairs = (tile == NTILES-1) ? 2 : 4;
            for (int p = 0; p < npairs; ++p) {
                uint32_t ba = bb + (unsigned)p*(16*BROW*2);
                uint32_t Bf[KC][4];
                #pragma unroll
                for (int kc = 0; kc < KC; ++kc) {
                    asm volatile("ldmatrix.sync.aligned.m8n8.x4.shared.b16 {%0,%1,%2,%3}, [%4];"
                        : "=r"(Bf[kc][0]), "=r"(Bf[kc][1]), "=r"(Bf[kc][2]), "=r"(Bf[kc][3])
                        : "r"(ba + kc*32));
                }
                #pragma unroll
                for (int mh = 0; mh < 2; ++mh) {
                    float d0[4] = {0.f,0.f,0.f,0.f}, d1[4] = {0.f,0.f,0.f,0.f};
                    #pragma unroll
                    for (int kc = 0; kc < KC; ++kc) {
                        asm volatile("mma.sync.aligned.m16n8k16.row.col.f32.bf16.bf16.f32 "
                            "{%0,%1,%2,%3}, {%4,%5,%6,%7}, {%8,%9}, {%0,%1,%2,%3};"
                            : "+f"(d0[0]), "+f"(d0[1]), "+f"(d0[2]), "+f"(d0[3])
                            : "r"(Af[kc][mh][0]), "r"(Af[kc][mh][1]),
                              "r"(Af[kc][mh][2]), "r"(Af[kc][mh][3]),
                              "r"(Bf[kc][0]), "r"(Bf[kc][1]));
                        asm volatile("mma.sync.aligned.m16n8k16.row.col.f32.bf16.bf16.f32 "
                            "{%0,%1,%2,%3}, {%4,%5,%6,%7}, {%8,%9}, {%0,%1,%2,%3};"
                            : "+f"(d1[0]), "+f"(d1[1]), "+f"(d1[2]), "+f"(d1[3])
                            : "r"(Af[kc][mh][0]), "r"(Af[kc][mh][1]),
                              "r"(Af[kc][mh][2]), "r"(Af[kc][mh][3]),
                              "r"(Bf[kc][2]), "r"(Bf[kc][3]));
                    }
                    if (mh == 0) {
                        topk_insert(tk0, d0[0]); topk_insert(tk0, d0[1]);
                        topk_insert(tk1, d0[2]); topk_insert(tk1, d0[3]);
                        topk_insert(tk0, d1[0]); topk_insert(tk0, d1[1]);
                        topk_insert(tk1, d1[2]); topk_insert(tk1, d1[3]);
                    } else {
                        topk_insert(tk2, d0[0]); topk_insert(tk2, d0[1]);
                        topk_insert(tk3, d0[2]); topk_insert(tk3, d0[3]);
                        topk_insert(tk2, d1[0]); topk_insert(tk2, d1[1]);
                        topk_insert(tk3, d1[2]); topk_insert(tk3, d1[3]);
                    }
                }
            }
        }

        // merge: 4 thread-local lists per row (lane&3) via smem [128][40]
        __syncthreads();
        float* mg = (float*)smraw;
        int g = lane >> 2, i4 = lane & 3;
        int base_r = w*32 + g;
        #pragma unroll
        for (int qq = 0; qq < TOPK; ++qq) {
            mg[(base_r     )*40 + i4*TOPK + qq] = tk0[qq];
            mg[(base_r + 8 )*40 + i4*TOPK + qq] = tk1[qq];
            mg[(base_r + 16)*40 + i4*TOPK + qq] = tk2[qq];
            mg[(base_r + 24)*40 + i4*TOPK + qq] = tk3[qq];
        }
        __syncthreads();
        {
            int row = rbase + t;
            if (row < N_NODE) {
                float m[TOPK];
                #pragma unroll
                for (int qq = 0; qq < TOPK; ++qq) m[qq] = -INFINITY;
                for (int qq = 0; qq < 4*TOPK; ++qq) topk_insert(m, mg[t*40 + qq]);
                #pragma unroll
                for (int qq = 0; qq < TOPK; ++qq)
                    g_qtk[((size_t)row*NQ + q)*TOPK + qq] = m[qq] * INV_TEMP;
            }
        }
    }
}

// ---------------- cl merge ----------------
__global__ void k_cl_merge(float* __restrict__ out_cl) {
    __shared__ float sh[256];
    int idx = blockIdx.x * 256 + threadIdx.x;
    float contrib = 0.0f;
    if (idx < N_NODE) {
        float m[TOPK];
        #pragma unroll
        for (int q = 0; q < TOPK; ++q) m[q] = -INFINITY;
        const float* p = g_qtk + (size_t)idx*NQ*TOPK;
        for (int q = 0; q < NQ*TOPK; ++q) topk_insert(m, p[q]);
        float se = 0.0f;
        #pragma unroll
        for (int q = 1; q < TOPK; ++q) se += __expf(m[q] - m[0]);
        contrib = log1pf(se) * (CL_WF / (float)N_NODE);
    }
    sh[threadIdx.x] = contrib; __syncthreads();
    for (int s = 128; s > 0; s >>= 1) {
        if (threadIdx.x < s) sh[threadIdx.x] += sh[threadIdx.x + s];
        __syncthreads();
    }
    if (threadIdx.x == 0) atomicAdd(out_cl, sh[0]);
}

// ---------------- launch ----------------
extern "C" void kernel_launch(void* const* d_in, const int* in_sizes, int n_in,
                              void* d_out, int out_size) {
    const float* slen  = (const float*)d_in[1];
    const int*   rev   = (const int*)d_in[2];
    const int*   mask  = (const int*)d_in[3];
    const int*   tar   = (const int*)d_in[5];
    const int*   arow  = (const int*)d_in[8];
    const int*   acol  = (const int*)d_in[9];
    const float* avals = (const float*)d_in[10];
    const float* emb   = (const float*)d_in[11];
    const float* pos   = (const float*)d_in[12];
    const float* witem = (const float*)d_in[13];
    const float* attw  = (const float*)d_in[14];
    const float* attb  = (const float*)d_in[15];
    const float* w1    = (const float*)d_in[16];
    const float* w2    = (const float*)d_in[17];
    const float* glu1  = (const float*)d_in[18];
    const float* glu1b = (const float*)d_in[19];
    const float* glu2  = (const float*)d_in[20];
    float* out = (float*)d_out;
    int E = in_sizes[8];

    cudaFuncSetAttribute(k_cl_tc, cudaFuncAttributeMaxDynamicSharedMemorySize, CL_SMEM);
    cudaFuncSetAttribute(k_scores, cudaFuncAttributeMaxDynamicSharedMemorySize, SC_SMEM);
    cudaFuncSetAttribute(k_lin_att, cudaFuncAttributeMaxDynamicSharedMemorySize,
                         (EMB*EMB + 64*EMB)*4);
    cudaFuncSetAttribute(k_nh, cudaFuncAttributeMaxDynamicSharedMemorySize, NH_SMEM);
    cudaFuncSetAttribute(k_beta, cudaFuncAttributeMaxDynamicSharedMemorySize, NB_SMEM);

    k_init<<<2048, 256>>>(emb, out, out_size);
    k_transpose<<<(N_LAYERS*EMB*EMB + 255)/256, 256>>>(witem, glu1, glu2);
    k_posw<<<SEQ, 128>>>(pos, w1);
    k_prep<<<(E + 255)/256, 256>>>(arow, acol, avals, E);
    k_scan<<<1, 1024>>>();
    k_scatter<<<(E + 255)/256, 256>>>(arow, acol, avals, E);

    for (int l = 0; l < N_LAYERS; ++l) {
        k_att_score<<<(N_NODE*32 + 255)/256, 256>>>(attw, attb);
        k_softmax_reduce<<<1, 1024>>>();
        k_lin_att<<<(N_NODE + 63)/64, 256, (EMB*EMB + 64*EMB)*4>>>(l);
        k_spmm_csr<<<(N_NODE*32 + 255)/256, 256>>>();
    }

    k_item<<<(N_NODE*32 + 255)/256, 256>>>();

    // session pipeline: parallel over (b, l) — two batched GEMMs instead of a 50-step loop
    k_sess_pre<<<BATCH, 128>>>(rev, slen);
    k_nh<<<NROWS_S/64, 256, NH_SMEM>>>(w1 + EMB*EMB);   // w1half = rows [100..200)
    k_beta<<<NROWS_S/64, 256, NB_SMEM>>>(mask, w2, glu1b);
    k_sessagg<<<BATCH, 128>>>();
    k_sess_norm<<<(BATCH*32 + 255)/256, 256>>>();

    dim3 sg((N_NODE + 127)/128, BATCH/64);
    k_scores<<<sg, 256, SC_SMEM>>>(out + 1);

    k_loss<<<BATCH, 256>>>(out + 1, tar, out);
    k_cl_tc<<<CLGRID, 128, CL_SMEM>>>();
    k_cl_merge<<<(N_NODE + 255)/256, 256>>>(out + out_size - 1);
}

// round 13
// speedup vs baseline: 1.3371x; 1.0093x over previous
#include <cuda_runtime.h>
#include <cuda_bf16.h>
#include <math.h>
#include <stdint.h>

#define N_NODE 20000
#define EMB 100
#define BATCH 512
#define SEQ 50
#define N_LAYERS 2
#define INV_TEMP 10.0f
#define W_KF 10.0f
#define TOPK 10
#define CL_WF 100.0f
#define EPSN 1e-12f
#define EMAX 345000
#define NROWS_S (BATCH*SEQ)     // 25600

// mma.sync cl gemm tiling
#define KPAD 112                // K padded to 7*16
#define KC 7
#define CLM 128                 // rows per CTA
#define CLN 128                 // cols per tile (widened: fewer tiles, less per-tile overhead)
#define NBLK 157                // ceil(20000/128)
#define ROWS_PAD (NBLK*CLM)     // 20096
#define NT2 157                 // ceil(20000/128) col tiles
#define BROW 120                // smem row stride in halves (240B)
#define NQ 8
#define NITEMS (NBLK*NQ)        // 1256
#define CLGRID 296
#define A_BYTES (CLM*BROW*2)    // 30720
#define B_BYTES (CLN*BROW*2)    // 30720
#define CL_SMEM (A_BYTES + 2*B_BYTES)  // 92160

// ---------------- scratch ----------------
__device__ float g_colsum[N_NODE];
__device__ int   g_cnt[N_NODE];
__device__ int   g_rowptr[N_NODE+1];
__device__ int   g_cursor[N_NODE];
__device__ int   g_ecol[EMAX];
__device__ float g_eval[EMAX];
__device__ int   g_work;
__device__ float g_x[N_NODE*EMB];
__device__ float g_y[N_NODE*EMB];
__device__ float g_final[N_NODE*EMB];
__device__ float g_item[N_NODE*EMB];
__device__ float g_itemn[N_NODE*EMB];
__device__ float g_s[N_NODE];
__device__ float g_asum;
__device__ float g_wT[N_LAYERS*EMB*EMB];
__device__ float g_glu1T[EMB*EMB];
__device__ float g_glu2T[EMB*EMB];
__device__ float g_sess[BATCH*EMB];
__device__ float g_sessn[BATCH*EMB];
__device__ float g_posw[SEQ*EMB];
__device__ float g_seqh[(size_t)NROWS_S*EMB];   // 10.24 MB
__device__ float g_hsg[BATCH*EMB];
__device__ float g_beta[NROWS_S];
__device__ float g_qtk[(size_t)ROWS_PAD*NQ*TOPK];
__device__ __align__(16) __nv_bfloat16 g_bf16[(size_t)ROWS_PAD*KPAD];

// ---------------- helpers ----------------
__device__ __forceinline__ float warp_sum(float v) {
    #pragma unroll
    for (int o = 16; o > 0; o >>= 1) v += __shfl_xor_sync(0xffffffffu, v, o);
    return v;
}

__device__ __forceinline__ void topk_insert(float (&tk)[TOPK], float v) {
    if (v > tk[TOPK-1]) {
        tk[TOPK-1] = v;
        #pragma unroll
        for (int i = TOPK-1; i > 0; --i) {
            if (tk[i] > tk[i-1]) { float tmp = tk[i-1]; tk[i-1] = tk[i]; tk[i] = tmp; }
        }
    }
}

// ---------------- init ----------------
__global__ void k_init(const float* __restrict__ emb, float* __restrict__ out, int out_size) {
    int stride = gridDim.x * blockDim.x;
    int i0 = blockIdx.x * blockDim.x + threadIdx.x;
    for (int i = i0; i < N_NODE*EMB; i += stride) {
        float v = emb[i];
        g_x[i] = v;
        g_final[i] = v;
        if (i < N_NODE) { g_colsum[i] = 0.0f; g_cnt[i] = 0; }
    }
    for (int i = i0; i < (ROWS_PAD - N_NODE)*KPAD; i += stride)
        g_bf16[(size_t)N_NODE*KPAD + i] = __float2bfloat16(0.0f);
    if (i0 == 0) { out[0] = 0.0f; out[out_size-1] = 0.0f; g_work = 0; g_asum = 0.0f; }
}

// ---------------- transpose weights ----------------
__global__ void k_transpose(const float* __restrict__ w_item,
                            const float* __restrict__ glu1,
                            const float* __restrict__ glu2) {
    int i = blockIdx.x * blockDim.x + threadIdx.x;
    if (i < N_LAYERS*EMB*EMB) {
        int l = i / (EMB*EMB);
        int r = i - l*(EMB*EMB);
        int j = r / EMB, k = r - j*EMB;
        g_wT[l*EMB*EMB + j*EMB + k] = w_item[l*EMB*EMB + k*EMB + j];
    }
    if (i < EMB*EMB) {
        int j = i / EMB, k = i - j*EMB;
        g_glu1T[j*EMB + k] = glu1[k*EMB + j];
        g_glu2T[j*EMB + k] = glu2[k*EMB + j];
    }
}

// ---------------- posW ----------------
__global__ void k_posw(const float* __restrict__ pos, const float* __restrict__ w1) {
    int l = blockIdx.x, t = threadIdx.x;
    if (t < EMB) {
        float acc = 0.0f;
        for (int j = 0; j < EMB; ++j) acc += pos[l*EMB + j] * w1[j*EMB + t];
        g_posw[l*EMB + t] = acc;
    }
}

// ---------------- edge pass: column sums + row degrees ----------------
__global__ void k_prep(const int* __restrict__ row, const int* __restrict__ col,
                       const float* __restrict__ vals, int E) {
    int e = blockIdx.x * blockDim.x + threadIdx.x;
    if (e < E) {
        atomicAdd(&g_colsum[col[e]], vals[e]);
        atomicAdd(&g_cnt[row[e]], 1);
    }
}

// ---------------- prefix sum -> rowptr ----------------
__global__ void k_scan() {
    __shared__ int sh[1024];
    int t = threadIdx.x;
    const int CH = 20;
    int local[CH];
    int s = 0;
    #pragma unroll
    for (int i = 0; i < CH; ++i) {
        int idx = t*CH + i;
        int c = (idx < N_NODE) ? g_cnt[idx] : 0;
        local[i] = s; s += c;
    }
    sh[t] = s; __syncthreads();
    for (int off = 1; off < 1024; off <<= 1) {
        int v = (t >= off) ? sh[t-off] : 0;
        __syncthreads();
        if (t >= off) sh[t] += v;
        __syncthreads();
    }
    int base = (t == 0) ? 0 : sh[t-1];
    #pragma unroll
    for (int i = 0; i < CH; ++i) {
        int idx = t*CH + i;
        if (idx < N_NODE) {
            int p = base + local[i];
            g_rowptr[idx] = p;
            g_cursor[idx] = p;
        }
    }
    if (t == 1023) g_rowptr[N_NODE] = sh[1023];
}

// ---------------- scatter edges into CSR ----------------
__global__ void k_scatter(const int* __restrict__ row, const int* __restrict__ col,
                          const float* __restrict__ vals, int E) {
    int e = blockIdx.x * blockDim.x + threadIdx.x;
    if (e >= E) return;
    int c = col[e], r = row[e];
    float v = vals[e] / g_colsum[c];
    int p = atomicAdd(&g_cursor[r], 1);
    g_ecol[p] = c;
    g_eval[p] = v;
}

// ---------------- attention scores + fused exp-sum (no max-sub: |s| <= ~1) ----------------
__global__ void k_att_score(const float* __restrict__ attw, const float* __restrict__ attb) {
    __shared__ float shw[8];
    int gw = (blockIdx.x * blockDim.x + threadIdx.x) >> 5;
    int wid = threadIdx.x >> 5;
    int lane = threadIdx.x & 31;
    float e = 0.0f;
    if (gw < N_NODE) {
        const float* xr = g_x + gw*EMB;
        float acc = 0.0f;
        for (int k = lane; k < EMB; k += 32) acc += xr[k] * attw[k];
        acc = warp_sum(acc);
        if (lane == 0) {
            float s = acc + attb[0];
            g_s[gw] = s;
            e = __expf(s);
        }
    }
    if (lane == 0) shw[wid] = e;
    __syncthreads();
    if (threadIdx.x == 0) {
        float tot = 0.0f;
        #pragma unroll
        for (int i = 0; i < 8; ++i) tot += shw[i];
        atomicAdd(&g_asum, tot);
    }
}

// ---------------- y = (x @ W^T) * att  (WT staged in smem) ----------------
__global__ void k_lin_att(int layer) {
    extern __shared__ float sm_la[];
    float* WT = sm_la;            // [100][100]
    float* xs = sm_la + EMB*EMB;  // [64][100]
    int base = blockIdx.x * 64;
    int t = threadIdx.x;
    int nvalid = min(64, N_NODE - base);
    const float* WTg = g_wT + layer*EMB*EMB;
    for (int i = t; i < EMB*EMB; i += 256) WT[i] = WTg[i];
    for (int i = t; i < nvalid*EMB; i += 256) xs[i] = g_x[base*EMB + i];
    __syncthreads();
    float inv = 1.0f / g_asum;
    int npairs = nvalid * 25;
    for (int p = t; p < npairs; p += 256) {
        int n = p / 25, k4 = p - n*25;
        float a0 = 0.f, a1 = 0.f, a2 = 0.f, a3 = 0.f;
        const float* xr = xs + n*EMB;
        #pragma unroll 4
        for (int j = 0; j < EMB; ++j) {
            float xv = xr[j];
            float4 wv = *(const float4*)&WT[j*EMB + k4*4];
            a0 += xv*wv.x; a1 += xv*wv.y; a2 += xv*wv.z; a3 += xv*wv.w;
        }
        float att = __expf(g_s[base + n]) * inv;
        float4 o = make_float4(a0*att, a1*att, a2*att, a3*att);
        *(float4*)(g_y + (size_t)(base + n)*EMB + k4*4) = o;
    }
}

// ---------------- CSR SpMM fused with l2norm + final accumulate ----------------
__global__ void k_spmm_csr() {
    // reset softmax accumulator for the next layer's fused att_score
    if (blockIdx.x == 0 && threadIdx.x == 0) g_asum = 0.0f;
    int gw = (blockIdx.x * blockDim.x + threadIdx.x) >> 5;
    int lane = threadIdx.x & 31;
    if (gw >= N_NODE) return;
    int s = g_rowptr[gw], e = g_rowptr[gw+1];
    bool act = lane < 25;
    float4 acc = make_float4(0.f, 0.f, 0.f, 0.f);
    for (int i = s; i < e; ++i) {
        int c = g_ecol[i];
        float v = g_eval[i];
        if (act) {
            float4 yv = *(const float4*)(g_y + (size_t)c*EMB + lane*4);
            acc.x += v*yv.x; acc.y += v*yv.y; acc.z += v*yv.z; acc.w += v*yv.w;
        }
    }
    float ss = acc.x*acc.x + acc.y*acc.y + acc.z*acc.z + acc.w*acc.w;
    ss = warp_sum(ss);
    float invn = 1.0f / fmaxf(sqrtf(ss), EPSN);
    if (act) {
        float4 nv = make_float4(acc.x*invn, acc.y*invn, acc.z*invn, acc.w*invn);
        *(float4*)(g_x + (size_t)gw*EMB + lane*4) = nv;
        float4 f = *(const float4*)(g_final + (size_t)gw*EMB + lane*4);
        f.x += nv.x; f.y += nv.y; f.z += nv.z; f.w += nv.w;
        *(float4*)(g_final + (size_t)gw*EMB + lane*4) = f;
    }
}

// ---------------- item_emb = final/3 ; item_n = l2norm ; bf16 ----------------
__global__ void k_item() {
    int gw = (blockIdx.x * blockDim.x + threadIdx.x) >> 5;
    int lane = threadIdx.x & 31;
    if (gw >= N_NODE) return;
    const float inv3 = 1.0f / 3.0f;
    float ss = 0.0f;
    float v[4];
    #pragma unroll
    for (int i = 0; i < 4; ++i) {
        int k = lane + 32*i;
        v[i] = (k < EMB) ? g_final[gw*EMB + k] * inv3 : 0.0f;
        ss += v[i]*v[i];
    }
    ss = warp_sum(ss);
    float invn = 1.0f / fmaxf(sqrtf(ss), EPSN);
    #pragma unroll
    for (int i = 0; i < 4; ++i) {
        int k = lane + 32*i;
        if (k < EMB) {
            float nv = v[i] * invn;
            g_item[gw*EMB + k]  = v[i];
            g_itemn[gw*EMB + k] = nv;
            g_bf16[(size_t)gw*KPAD + k] = __float2bfloat16(nv);
        }
    }
    if (lane < KPAD - EMB) g_bf16[(size_t)gw*KPAD + EMB + lane] = __float2bfloat16(0.0f);
}

// ---------------- sess stage 1: gather seq_h, compute hs -> hsg ----------------
__global__ void k_sess_pre(const int* __restrict__ rev, const float* __restrict__ slen) {
    __shared__ float sh_seq[SEQ*EMB];
    __shared__ float sh_hs[EMB];
    int b = blockIdx.x, t = threadIdx.x;
    for (int idx = t; idx < SEQ*EMB; idx += 128) {
        int l = idx / EMB, k = idx - l*EMB;
        int id = rev[b*SEQ + l];
        float v = (id == 0) ? 0.0f : g_item[(size_t)(id-1)*EMB + k];
        sh_seq[idx] = v;
        g_seqh[(size_t)b*SEQ*EMB + idx] = v;
    }
    __syncthreads();
    if (t < EMB) {
        float acc = 0.0f;
        for (int l = 0; l < SEQ; ++l) acc += sh_seq[l*EMB + t];
        sh_hs[t] = acc / slen[b];
    }
    __syncthreads();
    if (t < EMB) {
        float p0=0.f,p1=0.f,p2=0.f,p3=0.f;
        for (int j = 0; j < EMB; j += 4) {
            p0 += sh_hs[j]   * g_glu2T[j*EMB + t];
            p1 += sh_hs[j+1] * g_glu2T[(j+1)*EMB + t];
            p2 += sh_hs[j+2] * g_glu2T[(j+2)*EMB + t];
            p3 += sh_hs[j+3] * g_glu2T[(j+3)*EMB + t];
        }
        g_hsg[b*EMB + t] = (p0+p1)+(p2+p3);
    }
}

// ---- sess stages 2+3 fused: nh = tanh(posw + seq_h@w1h) kept in smem; beta = w2.sigmoid(nh@glu1T + b + hsg) ----
#define NB_SMEM ((EMB*EMB + 64*EMB + 64*EMB + 64)*4)   // W 40000 + xs 25600 + nh 25600 + sb 256
__global__ __launch_bounds__(256) void k_nhbeta(const float* __restrict__ w1h,
                                                const int* __restrict__ mask,
                                                const float* __restrict__ w2,
                                                const float* __restrict__ glu1b) {
    extern __shared__ float sm_nb[];
    float* W  = sm_nb;                      // [100][100] (w1half, then reused for glu1T)
    float* xs = sm_nb + EMB*EMB;            // [64][100] seq_h tile
    float* nh = sm_nb + EMB*EMB + 64*EMB;   // [64][100]
    float* sb = sm_nb + EMB*EMB + 2*64*EMB; // [64]
    int base = blockIdx.x * 64;
    int t = threadIdx.x;
    for (int i = t; i < EMB*EMB; i += 256) W[i] = w1h[i];
    for (int i = t; i < 64*EMB; i += 256) xs[i] = g_seqh[(size_t)base*EMB + i];
    if (t < 64) sb[t] = 0.0f;
    __syncthreads();
    // stage 2: nh
    for (int p = t; p < 64*25; p += 256) {
        int n = p / 25, k4 = p - n*25;
        float a0 = 0.f, a1 = 0.f, a2 = 0.f, a3 = 0.f;
        const float* xr = xs + n*EMB;
        #pragma unroll 4
        for (int j = 0; j < EMB; ++j) {
            float xv = xr[j];
            float4 wv = *(const float4*)&W[j*EMB + k4*4];
            a0 += xv*wv.x; a1 += xv*wv.y; a2 += xv*wv.z; a3 += xv*wv.w;
        }
        int r = base + n;
        int l = r - (r / SEQ) * SEQ;
        float4 pw = *(const float4*)&g_posw[l*EMB + k4*4];
        nh[n*EMB + k4*4 + 0] = tanhf(pw.x + a0);
        nh[n*EMB + k4*4 + 1] = tanhf(pw.y + a1);
        nh[n*EMB + k4*4 + 2] = tanhf(pw.z + a2);
        nh[n*EMB + k4*4 + 3] = tanhf(pw.w + a3);
    }
    __syncthreads();
    // re-stage W <- glu1T
    for (int i = t; i < EMB*EMB; i += 256) W[i] = g_glu1T[i];
    __syncthreads();
    // stage 3: beta
    for (int p = t; p < 64*25; p += 256) {
        int n = p / 25, k4 = p - n*25;
        float a0 = 0.f, a1 = 0.f, a2 = 0.f, a3 = 0.f;
        const float* xr = nh + n*EMB;
        #pragma unroll 4
        for (int j = 0; j < EMB; ++j) {
            float xv = xr[j];
            float4 gv = *(const float4*)&W[j*EMB + k4*4];
            a0 += xv*gv.x; a1 += xv*gv.y; a2 += xv*gv.z; a3 += xv*gv.w;
        }
        int r = base + n;
        int b = r / SEQ;
        float4 hb = *(const float4*)&g_hsg[b*EMB + k4*4];
        float4 bb = *(const float4*)&glu1b[k4*4];
        float4 wv = *(const float4*)&w2[k4*4];
        float c = 0.0f;
        c += wv.x / (1.0f + __expf(-(a0 + bb.x + hb.x)));
        c += wv.y / (1.0f + __expf(-(a1 + bb.y + hb.y)));
        c += wv.z / (1.0f + __expf(-(a2 + bb.z + hb.z)));
        c += wv.w / (1.0f + __expf(-(a3 + bb.w + hb.w)));
        atomicAdd(&sb[n], c);
    }
    __syncthreads();
    if (t < 64) {
        int r = base + t;
        int b = r / SEQ, l = r - b*SEQ;
        g_beta[r] = sb[t] * (float)mask[b*SEQ + l];
    }
}

// ---------------- sess stage 4: sess[b] = sum_l beta * seq_h ----------------
__global__ void k_sessagg() {
    __shared__ float bet[SEQ];
    int b = blockIdx.x, t = threadIdx.x;
    if (t < SEQ) bet[t] = g_beta[b*SEQ + t];
    __syncthreads();
    if (t < EMB) {
        float s = 0.0f;
        const float* sq = g_seqh + (size_t)b*SEQ*EMB + t;
        #pragma unroll 5
        for (int l = 0; l < SEQ; ++l) s += bet[l] * sq[l*EMB];
        g_sess[b*EMB + t] = s;
    }
}

// ---------------- sess = W_K * l2norm(sess) ----------------
__global__ void k_sess_norm() {
    int gw = (blockIdx.x * blockDim.x + threadIdx.x) >> 5;
    int lane = threadIdx.x & 31;
    if (gw >= BATCH) return;
    float ss = 0.0f;
    float v[4];
    #pragma unroll
    for (int i = 0; i < 4; ++i) {
        int k = lane + 32*i;
        v[i] = (k < EMB) ? g_sess[gw*EMB + k] : 0.0f;
        ss += v[i]*v[i];
    }
    ss = warp_sum(ss);
    float sc = W_KF / fmaxf(sqrtf(ss), EPSN);
    #pragma unroll
    for (int i = 0; i < 4; ++i) {
        int k = lane + 32*i;
        if (k < EMB) g_sessn[gw*EMB + k] = v[i] * sc;
    }
}

// ---------------- scores: 128 items x 64 sessions per block ----------------
#define SC_SMEM ((128*EMB + 64*EMB)*4)
__global__ __launch_bounds__(256) void k_scores(float* __restrict__ scores) {
    extern __shared__ float sm_sc[];
    float* its = sm_sc;
    float* ses = sm_sc + 128*EMB;
    int t = threadIdx.x;
    int nb = blockIdx.x * 128;
    int bb = blockIdx.y * 64;
    for (int i = t; i < 128*EMB; i += 256) {
        int item = nb + i / EMB;
        its[i] = (item < N_NODE) ? g_itemn[(size_t)nb*EMB + i] : 0.0f;
    }
    for (int i = t; i < 64*EMB; i += 256) ses[i] = g_sessn[(size_t)bb*EMB + i];
    __syncthreads();
    int ic = t & 31, sg = t >> 5;
    float acc[8][4];
    #pragma unroll
    for (int j = 0; j < 8; ++j)
        #pragma unroll
        for (int ii = 0; ii < 4; ++ii) acc[j][ii] = 0.0f;
    for (int k4 = 0; k4 < 25; ++k4) {
        float4 iv[4];
        #pragma unroll
        for (int ii = 0; ii < 4; ++ii)
            iv[ii] = *(const float4*)&its[(ic + 32*ii)*EMB + k4*4];
        #pragma unroll
        for (int j = 0; j < 8; ++j) {
            float4 sv = *(const float4*)&ses[(sg*8 + j)*EMB + k4*4];
            #pragma unroll
            for (int ii = 0; ii < 4; ++ii)
                acc[j][ii] += iv[ii].x*sv.x + iv[ii].y*sv.y + iv[ii].z*sv.z + iv[ii].w*sv.w;
        }
    }
    #pragma unroll
    for (int j = 0; j < 8; ++j) {
        int b = bb + sg*8 + j;
        #pragma unroll
        for (int ii = 0; ii < 4; ++ii) {
            int col = nb + ic + 32*ii;
            if (col < N_NODE) scores[(size_t)b * N_NODE + col] = acc[j][ii];
        }
    }
}

// ---------------- loss_item: online CE ----------------
__global__ void k_loss(const float* __restrict__ scores, const int* __restrict__ tar,
                       float* __restrict__ out0) {
    __shared__ float shm[256], shs[256];
    int b = blockIdx.x, t = threadIdx.x;
    const float* row = scores + (size_t)b * N_NODE;
    float m = -INFINITY, s = 0.0f;
    for (int i = t; i < N_NODE; i += 256) {
        float v = row[i];
        if (v > m) { s = s * __expf(m - v) + 1.0f; m = v; }
        else       { s += __expf(v - m); }
    }
    shm[t] = m; shs[t] = s; __syncthreads();
    for (int o = 128; o > 0; o >>= 1) {
        if (t < o) {
            float m2 = shm[t+o], s2 = shs[t+o];
            float M = fmaxf(shm[t], m2);
            shs[t] = shs[t]*__expf(shm[t]-M) + s2*__expf(m2-M);
            shm[t] = M;
        }
        __syncthreads();
    }
    if (t == 0) {
        float lse = shm[0] + logf(shs[0]);
        atomicAdd(out0, (lse - row[tar[b]]) * (1.0f / BATCH));
    }
}

// ---------------- cl GEMM: mma.sync persistent, CLN=128 tiles, fused top-10 ----------------
__global__ __launch_bounds__(128) void k_cl_tc() {
    extern __shared__ __align__(16) char smraw[];   // A 30720 | B0 30720 | B1 30720
    __shared__ int sh_item;
    uint32_t sbase = (uint32_t)__cvta_generic_to_shared(smraw);
    int t = threadIdx.x, lane = t & 31, w = t >> 5;

    for (;;) {
        __syncthreads();
        if (t == 0) sh_item = atomicAdd(&g_work, 1);
        __syncthreads();
        int item = sh_item;
        if (item >= NITEMS) return;
        int rowblk = item >> 3, q = item & 7;
        int rbase = rowblk * CLM;
        int qs = (q * NT2) / NQ, qe = ((q + 1) * NT2) / NQ;

        // stage A tile: 128 rows x 112 halves
        const __nv_bfloat16* Ag = g_bf16 + (size_t)rbase * KPAD;
        for (int idx = t; idx < CLM*14; idx += 128) {
            int r = idx / 14, c = idx - r*14;
            *(uint4*)(smraw + (r*BROW + c*8)*2) = *(const uint4*)(Ag + r*KPAD + c*8);
        }
        __syncthreads();

        // A fragments: warp w owns rows w*32..w*32+31; two m16 halves
        uint32_t Af[KC][2][4];
        #pragma unroll
        for (int mh = 0; mh < 2; ++mh) {
            uint32_t aaddr = sbase +
                ((unsigned)(w*32 + mh*16 + (lane & 15))*BROW + ((lane >> 4)*8)) * 2;
            #pragma unroll
            for (int kc = 0; kc < KC; ++kc) {
                asm volatile("ldmatrix.sync.aligned.m8n8.x4.shared.b16 {%0,%1,%2,%3}, [%4];"
                    : "=r"(Af[kc][mh][0]), "=r"(Af[kc][mh][1]),
                      "=r"(Af[kc][mh][2]), "=r"(Af[kc][mh][3])
                    : "r"(aaddr + kc*32));
            }
        }
        __syncthreads();

        // prologue: async-load first B tile (128 cols)
        {
            const __nv_bfloat16* Bg = g_bf16 + (size_t)qs * CLN * KPAD;
            uint32_t dst = sbase + A_BYTES + (uint32_t)(qs & 1) * B_BYTES;
            for (int idx = t; idx < CLN*14; idx += 128) {
                int r = idx / 14, c = idx - r*14;
                uint32_t d = dst + (unsigned)(r*BROW + c*8)*2;
                const void* s = Bg + r*KPAD + c*8;
                asm volatile("cp.async.cg.shared.global [%0], [%1], 16;" :: "r"(d), "l"(s));
            }
            asm volatile("cp.async.commit_group;" ::: "memory");
        }

        // 4 top-10 lists (raw units)
        float tk0[TOPK], tk1[TOPK], tk2[TOPK], tk3[TOPK];
        #pragma unroll
        for (int i = 0; i < TOPK; ++i) {
            tk0[i] = -INFINITY; tk1[i] = -INFINITY;
            tk2[i] = -INFINITY; tk3[i] = -INFINITY;
        }

        int quad = lane >> 3, r8 = lane & 7;
        uint32_t bth = ((unsigned)(r8 + 8*(quad >> 1))*BROW + (quad & 1)*8) * 2;

        for (int tile = qs; tile < qe; ++tile) {
            asm volatile("cp.async.wait_group 0;" ::: "memory");
            __syncthreads();
            if (tile + 1 < qe) {
                const __nv_bfloat16* Bg = g_bf16 + (size_t)(tile + 1) * CLN * KPAD;
                uint32_t dst = sbase + A_BYTES + (uint32_t)((tile + 1) & 1) * B_BYTES;
                for (int idx = t; idx < CLN*14; idx += 128) {
                    int r = idx / 14, c = idx - r*14;
                    uint32_t d = dst + (unsigned)(r*BROW + c*8)*2;
                    const void* s = Bg + r*KPAD + c*8;
                    asm volatile("cp.async.cg.shared.global [%0], [%1], 16;" :: "r"(d), "l"(s));
                }
                asm volatile("cp.async.commit_group;" ::: "memory");
            }
            uint32_t bb = sbase + A_BYTES + (uint32_t)(tile & 1)*B_BYTES + bth;
            int npairs = (tile == NT2-1) ? 2 : 8;   // last tile: cols 19968..19999
            for (int p = 0; p < npairs; ++p) {
                uint32_t ba = bb + (unsigned)p*(16*BROW*2);
                uint32_t Bf[KC][4];
                #pragma unroll
                for (int kc = 0; kc < KC; ++kc) {
                    asm volatile("ldmatrix.sync.aligned.m8n8.x4.shared.b16 {%0,%1,%2,%3}, [%4];"
                        : "=r"(Bf[kc][0]), "=r"(Bf[kc][1]), "=r"(Bf[kc][2]), "=r"(Bf[kc][3])
                        : "r"(ba + kc*32));
                }
                #pragma unroll
                for (int mh = 0; mh < 2; ++mh) {
                    float d0[4] = {0.f,0.f,0.f,0.f}, d1[4] = {0.f,0.f,0.f,0.f};
                    #pragma unroll
                    for (int kc = 0; kc < KC; ++kc) {
                        asm volatile("mma.sync.aligned.m16n8k16.row.col.f32.bf16.bf16.f32 "
                            "{%0,%1,%2,%3}, {%4,%5,%6,%7}, {%8,%9}, {%0,%1,%2,%3};"
                            : "+f"(d0[0]), "+f"(d0[1]), "+f"(d0[2]), "+f"(d0[3])
                            : "r"(Af[kc][mh][0]), "r"(Af[kc][mh][1]),
                              "r"(Af[kc][mh][2]), "r"(Af[kc][mh][3]),
                              "r"(Bf[kc][0]), "r"(Bf[kc][1]));
                        asm volatile("mma.sync.aligned.m16n8k16.row.col.f32.bf16.bf16.f32 "
                            "{%0,%1,%2,%3}, {%4,%5,%6,%7}, {%8,%9}, {%0,%1,%2,%3};"
                            : "+f"(d1[0]), "+f"(d1[1]), "+f"(d1[2]), "+f"(d1[3])
                            : "r"(Af[kc][mh][0]), "r"(Af[kc][mh][1]),
                              "r"(Af[kc][mh][2]), "r"(Af[kc][mh][3]),
                              "r"(Bf[kc][2]), "r"(Bf[kc][3]));
                    }
                    if (mh == 0) {
                        topk_insert(tk0, d0[0]); topk_insert(tk0, d0[1]);
                        topk_insert(tk1, d0[2]); topk_insert(tk1, d0[3]);
                        topk_insert(tk0, d1[0]); topk_insert(tk0, d1[1]);
                        topk_insert(tk1, d1[2]); topk_insert(tk1, d1[3]);
                    } else {
                        topk_insert(tk2, d0[0]); topk_insert(tk2, d0[1]);
                        topk_insert(tk3, d0[2]); topk_insert(tk3, d0[3]);
                        topk_insert(tk2, d1[0]); topk_insert(tk2, d1[1]);
                        topk_insert(tk3, d1[2]); topk_insert(tk3, d1[3]);
                    }
                }
            }
        }

        // merge: 4 thread-local lists per row (lane&3) via smem [128][40]
        __syncthreads();
        float* mg = (float*)smraw;
        int g = lane >> 2, i4 = lane & 3;
        int base_r = w*32 + g;
        #pragma unroll
        for (int qq = 0; qq < TOPK; ++qq) {
            mg[(base_r     )*40 + i4*TOPK + qq] = tk0[qq];
            mg[(base_r + 8 )*40 + i4*TOPK + qq] = tk1[qq];
            mg[(base_r + 16)*40 + i4*TOPK + qq] = tk2[qq];
            mg[(base_r + 24)*40 + i4*TOPK + qq] = tk3[qq];
        }
        __syncthreads();
        {
            int row = rbase + t;
            if (row < N_NODE) {
                float m[TOPK];
                #pragma unroll
                for (int qq = 0; qq < TOPK; ++qq) m[qq] = -INFINITY;
                for (int qq = 0; qq < 4*TOPK; ++qq) topk_insert(m, mg[t*40 + qq]);
                #pragma unroll
                for (int qq = 0; qq < TOPK; ++qq)
                    g_qtk[((size_t)row*NQ + q)*TOPK + qq] = m[qq] * INV_TEMP;
            }
        }
    }
}

// ---------------- cl merge ----------------
__global__ void k_cl_merge(float* __restrict__ out_cl) {
    __shared__ float sh[256];
    int idx = blockIdx.x * 256 + threadIdx.x;
    float contrib = 0.0f;
    if (idx < N_NODE) {
        float m[TOPK];
        #pragma unroll
        for (int q = 0; q < TOPK; ++q) m[q] = -INFINITY;
        const float* p = g_qtk + (size_t)idx*NQ*TOPK;
        for (int q = 0; q < NQ*TOPK; ++q) topk_insert(m, p[q]);
        float se = 0.0f;
        #pragma unroll
        for (int q = 1; q < TOPK; ++q) se += __expf(m[q] - m[0]);
        contrib = log1pf(se) * (CL_WF / (float)N_NODE);
    }
    sh[threadIdx.x] = contrib; __syncthreads();
    for (int s = 128; s > 0; s >>= 1) {
        if (threadIdx.x < s) sh[threadIdx.x] += sh[threadIdx.x + s];
        __syncthreads();
    }
    if (threadIdx.x == 0) atomicAdd(out_cl, sh[0]);
}

// ---------------- launch ----------------
extern "C" void kernel_launch(void* const* d_in, const int* in_sizes, int n_in,
                              void* d_out, int out_size) {
    const float* slen  = (const float*)d_in[1];
    const int*   rev   = (const int*)d_in[2];
    const int*   mask  = (const int*)d_in[3];
    const int*   tar   = (const int*)d_in[5];
    const int*   arow  = (const int*)d_in[8];
    const int*   acol  = (const int*)d_in[9];
    const float* avals = (const float*)d_in[10];
    const float* emb   = (const float*)d_in[11];
    const float* pos   = (const float*)d_in[12];
    const float* witem = (const float*)d_in[13];
    const float* attw  = (const float*)d_in[14];
    const float* attb  = (const float*)d_in[15];
    const float* w1    = (const float*)d_in[16];
    const float* w2    = (const float*)d_in[17];
    const float* glu1  = (const float*)d_in[18];
    const float* glu1b = (const float*)d_in[19];
    const float* glu2  = (const float*)d_in[20];
    float* out = (float*)d_out;
    int E = in_sizes[8];

    cudaFuncSetAttribute(k_cl_tc, cudaFuncAttributeMaxDynamicSharedMemorySize, CL_SMEM);
    cudaFuncSetAttribute(k_scores, cudaFuncAttributeMaxDynamicSharedMemorySize, SC_SMEM);
    cudaFuncSetAttribute(k_lin_att, cudaFuncAttributeMaxDynamicSharedMemorySize,
                         (EMB*EMB + 64*EMB)*4);
    cudaFuncSetAttribute(k_nhbeta, cudaFuncAttributeMaxDynamicSharedMemorySize, NB_SMEM);

    k_init<<<2048, 256>>>(emb, out, out_size);
    k_transpose<<<(N_LAYERS*EMB*EMB + 255)/256, 256>>>(witem, glu1, glu2);
    k_posw<<<SEQ, 128>>>(pos, w1);
    k_prep<<<(E + 255)/256, 256>>>(arow, acol, avals, E);
    k_scan<<<1, 1024>>>();
    k_scatter<<<(E + 255)/256, 256>>>(arow, acol, avals, E);

    for (int l = 0; l < N_LAYERS; ++l) {
        k_att_score<<<(N_NODE*32 + 255)/256, 256>>>(attw, attb);
        k_lin_att<<<(N_NODE + 63)/64, 256, (EMB*EMB + 64*EMB)*4>>>(l);
        k_spmm_csr<<<(N_NODE*32 + 255)/256, 256>>>();
    }

    k_item<<<(N_NODE*32 + 255)/256, 256>>>();

    // session pipeline: parallel over (b, l)
    k_sess_pre<<<BATCH, 128>>>(rev, slen);
    k_nhbeta<<<NROWS_S/64, 256, NB_SMEM>>>(w1 + EMB*EMB, mask, w2, glu1b);
    k_sessagg<<<BATCH, 128>>>();
    k_sess_norm<<<(BATCH*32 + 255)/256, 256>>>();

    dim3 sg((N_NODE + 127)/128, BATCH/64);
    k_scores<<<sg, 256, SC_SMEM>>>(out + 1);

    k_loss<<<BATCH, 256>>>(out + 1, tar, out);
    k_cl_tc<<<CLGRID, 128, CL_SMEM>>>();
    k_cl_merge<<<(N_NODE + 255)/256, 256>>>(out + out_size - 1);
}

// round 15
// speedup vs baseline: 1.3656x; 1.0213x over previous
#include <cuda_runtime.h>
#include <cuda_bf16.h>
#include <math.h>
#include <stdint.h>

#define N_NODE 20000
#define EMB 100
#define BATCH 512
#define SEQ 50
#define N_LAYERS 2
#define INV_TEMP 10.0f
#define W_KF 10.0f
#define TOPK 10
#define CL_WF 100.0f
#define EPSN 1e-12f
#define EMAX 345000
#define NROWS_S (BATCH*SEQ)     // 25600

// mma.sync cl gemm tiling
#define KPAD 112                // K padded to 7*16
#define KC 7
#define CLM 128                 // rows per CTA
#define CLN 128                 // cols per tile
#define NBLK 157                // ceil(20000/128)
#define ROWS_PAD (NBLK*CLM)     // 20096
#define NT2 157                 // col tiles
#define BROW 120                // smem row stride in halves (240B)
#define NQ 8
#define NITEMS (NBLK*NQ)        // 1256
#define CLGRID 296
#define A_BYTES (CLM*BROW*2)    // 30720
#define B_BYTES (CLN*BROW*2)    // 30720
#define CL_SMEM (A_BYTES + 2*B_BYTES)  // 92160

// ---------------- scratch ----------------
__device__ float g_colsum[N_NODE];
__device__ int   g_cnt[N_NODE];
__device__ int   g_rowptr[N_NODE+1];
__device__ int   g_cursor[N_NODE];
__device__ int   g_ecol[EMAX];
__device__ float g_eval[EMAX];
__device__ int   g_work;
__device__ float g_x[N_NODE*EMB];
__device__ float g_y[N_NODE*EMB];
__device__ float g_final[N_NODE*EMB];
__device__ float g_item[N_NODE*EMB];
__device__ float g_itemn[N_NODE*EMB];
__device__ float g_s[N_NODE];
__device__ float g_asum;
__device__ float g_wT[N_LAYERS*EMB*EMB];
__device__ float g_glu1T[EMB*EMB];
__device__ float g_glu2T[EMB*EMB];
__device__ float g_sess[BATCH*EMB];
__device__ float g_sessn[BATCH*EMB];
__device__ float g_posw[SEQ*EMB];
__device__ float g_seqh[(size_t)NROWS_S*EMB];
__device__ float g_hsg[BATCH*EMB];
__device__ float g_beta[NROWS_S];
__device__ float g_qtk[(size_t)ROWS_PAD*NQ*TOPK];
__device__ __align__(16) __nv_bfloat16 g_bf16[(size_t)ROWS_PAD*KPAD];

// ---------------- helpers ----------------
__device__ __forceinline__ float warp_sum(float v) {
    #pragma unroll
    for (int o = 16; o > 0; o >>= 1) v += __shfl_xor_sync(0xffffffffu, v, o);
    return v;
}

__device__ __forceinline__ void topk_insert(float (&tk)[TOPK], float v) {
    if (v > tk[TOPK-1]) {
        tk[TOPK-1] = v;
        #pragma unroll
        for (int i = TOPK-1; i > 0; --i) {
            if (tk[i] > tk[i-1]) { float tmp = tk[i-1]; tk[i-1] = tk[i]; tk[i] = tmp; }
        }
    }
}

// ---------------- init ----------------
__global__ void k_init(const float* __restrict__ emb, float* __restrict__ out, int out_size) {
    int stride = gridDim.x * blockDim.x;
    int i0 = blockIdx.x * blockDim.x + threadIdx.x;
    for (int i = i0; i < N_NODE*EMB; i += stride) {
        float v = emb[i];
        g_x[i] = v;
        g_final[i] = v;
        if (i < N_NODE) { g_colsum[i] = 0.0f; g_cnt[i] = 0; }
    }
    for (int i = i0; i < (ROWS_PAD - N_NODE)*KPAD; i += stride)
        g_bf16[(size_t)N_NODE*KPAD + i] = __float2bfloat16(0.0f);
    if (i0 == 0) { out[0] = 0.0f; out[out_size-1] = 0.0f; g_work = 0; g_asum = 0.0f; }
}

// ---------------- transpose weights ----------------
__global__ void k_transpose(const float* __restrict__ w_item,
                            const float* __restrict__ glu1,
                            const float* __restrict__ glu2) {
    int i = blockIdx.x * blockDim.x + threadIdx.x;
    if (i < N_LAYERS*EMB*EMB) {
        int l = i / (EMB*EMB);
        int r = i - l*(EMB*EMB);
        int j = r / EMB, k = r - j*EMB;
        g_wT[l*EMB*EMB + j*EMB + k] = w_item[l*EMB*EMB + k*EMB + j];
    }
    if (i < EMB*EMB) {
        int j = i / EMB, k = i - j*EMB;
        g_glu1T[j*EMB + k] = glu1[k*EMB + j];
        g_glu2T[j*EMB + k] = glu2[k*EMB + j];
    }
}

// ---------------- posW ----------------
__global__ void k_posw(const float* __restrict__ pos, const float* __restrict__ w1) {
    int l = blockIdx.x, t = threadIdx.x;
    if (t < EMB) {
        float acc = 0.0f;
        for (int j = 0; j < EMB; ++j) acc += pos[l*EMB + j] * w1[j*EMB + t];
        g_posw[l*EMB + t] = acc;
    }
}

// ---------------- edge pass: column sums + row degrees ----------------
__global__ void k_prep(const int* __restrict__ row, const int* __restrict__ col,
                       const float* __restrict__ vals, int E) {
    int e = blockIdx.x * blockDim.x + threadIdx.x;
    if (e < E) {
        atomicAdd(&g_colsum[col[e]], vals[e]);
        atomicAdd(&g_cnt[row[e]], 1);
    }
}

// ---------------- prefix sum -> rowptr ----------------
__global__ void k_scan() {
    __shared__ int sh[1024];
    int t = threadIdx.x;
    const int CH = 20;
    int local[CH];
    int s = 0;
    #pragma unroll
    for (int i = 0; i < CH; ++i) {
        int idx = t*CH + i;
        int c = (idx < N_NODE) ? g_cnt[idx] : 0;
        local[i] = s; s += c;
    }
    sh[t] = s; __syncthreads();
    for (int off = 1; off < 1024; off <<= 1) {
        int v = (t >= off) ? sh[t-off] : 0;
        __syncthreads();
        if (t >= off) sh[t] += v;
        __syncthreads();
    }
    int base = (t == 0) ? 0 : sh[t-1];
    #pragma unroll
    for (int i = 0; i < CH; ++i) {
        int idx = t*CH + i;
        if (idx < N_NODE) {
            int p = base + local[i];
            g_rowptr[idx] = p;
            g_cursor[idx] = p;
        }
    }
    if (t == 1023) g_rowptr[N_NODE] = sh[1023];
}

// ---------------- scatter edges into CSR ----------------
__global__ void k_scatter(const int* __restrict__ row, const int* __restrict__ col,
                          const float* __restrict__ vals, int E) {
    int e = blockIdx.x * blockDim.x + threadIdx.x;
    if (e >= E) return;
    int c = col[e], r = row[e];
    float v = vals[e] / g_colsum[c];
    int p = atomicAdd(&g_cursor[r], 1);
    g_ecol[p] = c;
    g_eval[p] = v;
}

// ---------------- attention scores + fused exp-sum (no max-sub: |s| <= ~1) ----------------
__global__ void k_att_score(const float* __restrict__ attw, const float* __restrict__ attb) {
    __shared__ float shw[8];
    int gw = (blockIdx.x * blockDim.x + threadIdx.x) >> 5;
    int wid = threadIdx.x >> 5;
    int lane = threadIdx.x & 31;
    float e = 0.0f;
    if (gw < N_NODE) {
        const float* xr = g_x + gw*EMB;
        float acc = 0.0f;
        for (int k = lane; k < EMB; k += 32) acc += xr[k] * attw[k];
        acc = warp_sum(acc);
        if (lane == 0) {
            float s = acc + attb[0];
            g_s[gw] = s;
            e = __expf(s);
        }
    }
    if (lane == 0) shw[wid] = e;
    __syncthreads();
    if (threadIdx.x == 0) {
        float tot = 0.0f;
        #pragma unroll
        for (int i = 0; i < 8; ++i) tot += shw[i];
        atomicAdd(&g_asum, tot);
    }
}

// ---------------- y = (x @ W^T) * att  (WT staged in smem) ----------------
__global__ void k_lin_att(int layer) {
    extern __shared__ float sm_la[];
    float* WT = sm_la;            // [100][100]
    float* xs = sm_la + EMB*EMB;  // [64][100]
    int base = blockIdx.x * 64;
    int t = threadIdx.x;
    int nvalid = min(64, N_NODE - base);
    const float* WTg = g_wT + layer*EMB*EMB;
    for (int i = t; i < EMB*EMB; i += 256) WT[i] = WTg[i];
    for (int i = t; i < nvalid*EMB; i += 256) xs[i] = g_x[base*EMB + i];
    __syncthreads();
    float inv = 1.0f / g_asum;
    int npairs = nvalid * 25;
    for (int p = t; p < npairs; p += 256) {
        int n = p / 25, k4 = p - n*25;
        float a0 = 0.f, a1 = 0.f, a2 = 0.f, a3 = 0.f;
        const float* xr = xs + n*EMB;
        #pragma unroll 4
        for (int j = 0; j < EMB; ++j) {
            float xv = xr[j];
            float4 wv = *(const float4*)&WT[j*EMB + k4*4];
            a0 += xv*wv.x; a1 += xv*wv.y; a2 += xv*wv.z; a3 += xv*wv.w;
        }
        float att = __expf(g_s[base + n]) * inv;
        float4 o = make_float4(a0*att, a1*att, a2*att, a3*att);
        *(float4*)(g_y + (size_t)(base + n)*EMB + k4*4) = o;
    }
}

// ---------------- CSR SpMM fused with l2norm + final accumulate ----------------
__global__ void k_spmm_csr() {
    if (blockIdx.x == 0 && threadIdx.x == 0) g_asum = 0.0f;
    int gw = (blockIdx.x * blockDim.x + threadIdx.x) >> 5;
    int lane = threadIdx.x & 31;
    if (gw >= N_NODE) return;
    int s = g_rowptr[gw], e = g_rowptr[gw+1];
    bool act = lane < 25;
    float4 acc = make_float4(0.f, 0.f, 0.f, 0.f);
    for (int i = s; i < e; ++i) {
        int c = g_ecol[i];
        float v = g_eval[i];
        if (act) {
            float4 yv = *(const float4*)(g_y + (size_t)c*EMB + lane*4);
            acc.x += v*yv.x; acc.y += v*yv.y; acc.z += v*yv.z; acc.w += v*yv.w;
        }
    }
    float ss = acc.x*acc.x + acc.y*acc.y + acc.z*acc.z + acc.w*acc.w;
    ss = warp_sum(ss);
    float invn = 1.0f / fmaxf(sqrtf(ss), EPSN);
    if (act) {
        float4 nv = make_float4(acc.x*invn, acc.y*invn, acc.z*invn, acc.w*invn);
        *(float4*)(g_x + (size_t)gw*EMB + lane*4) = nv;
        float4 f = *(const float4*)(g_final + (size_t)gw*EMB + lane*4);
        f.x += nv.x; f.y += nv.y; f.z += nv.z; f.w += nv.w;
        *(float4*)(g_final + (size_t)gw*EMB + lane*4) = f;
    }
}

// ---------------- item_emb = final/3 ; item_n = l2norm ; bf16 ----------------
__global__ void k_item() {
    int gw = (blockIdx.x * blockDim.x + threadIdx.x) >> 5;
    int lane = threadIdx.x & 31;
    if (gw >= N_NODE) return;
    const float inv3 = 1.0f / 3.0f;
    float ss = 0.0f;
    float v[4];
    #pragma unroll
    for (int i = 0; i < 4; ++i) {
        int k = lane + 32*i;
        v[i] = (k < EMB) ? g_final[gw*EMB + k] * inv3 : 0.0f;
        ss += v[i]*v[i];
    }
    ss = warp_sum(ss);
    float invn = 1.0f / fmaxf(sqrtf(ss), EPSN);
    #pragma unroll
    for (int i = 0; i < 4; ++i) {
        int k = lane + 32*i;
        if (k < EMB) {
            float nv = v[i] * invn;
            g_item[gw*EMB + k]  = v[i];
            g_itemn[gw*EMB + k] = nv;
            g_bf16[(size_t)gw*KPAD + k] = __float2bfloat16(nv);
        }
    }
    if (lane < KPAD - EMB) g_bf16[(size_t)gw*KPAD + EMB + lane] = __float2bfloat16(0.0f);
}

// ---------------- sess stage 1: gather seq_h, compute hs -> hsg ----------------
__global__ void k_sess_pre(const int* __restrict__ rev, const float* __restrict__ slen) {
    __shared__ float sh_seq[SEQ*EMB];
    __shared__ float sh_hs[EMB];
    int b = blockIdx.x, t = threadIdx.x;
    for (int idx = t; idx < SEQ*EMB; idx += 128) {
        int l = idx / EMB, k = idx - l*EMB;
        int id = rev[b*SEQ + l];
        float v = (id == 0) ? 0.0f : g_item[(size_t)(id-1)*EMB + k];
        sh_seq[idx] = v;
        g_seqh[(size_t)b*SEQ*EMB + idx] = v;
    }
    __syncthreads();
    if (t < EMB) {
        float acc = 0.0f;
        for (int l = 0; l < SEQ; ++l) acc += sh_seq[l*EMB + t];
        sh_hs[t] = acc / slen[b];
    }
    __syncthreads();
    if (t < EMB) {
        float p0=0.f,p1=0.f,p2=0.f,p3=0.f;
        for (int j = 0; j < EMB; j += 4) {
            p0 += sh_hs[j]   * g_glu2T[j*EMB + t];
            p1 += sh_hs[j+1] * g_glu2T[(j+1)*EMB + t];
            p2 += sh_hs[j+2] * g_glu2T[(j+2)*EMB + t];
            p3 += sh_hs[j+3] * g_glu2T[(j+3)*EMB + t];
        }
        g_hsg[b*EMB + t] = (p0+p1)+(p2+p3);
    }
}

// ---- sess stages 2+3 fused ----
#define NB_SMEM ((EMB*EMB + 64*EMB + 64*EMB + 64)*4)
__global__ __launch_bounds__(256) void k_nhbeta(const float* __restrict__ w1h,
                                                const int* __restrict__ mask,
                                                const float* __restrict__ w2,
                                                const float* __restrict__ glu1b) {
    extern __shared__ float sm_nb[];
    float* W  = sm_nb;
    float* xs = sm_nb + EMB*EMB;
    float* nh = sm_nb + EMB*EMB + 64*EMB;
    float* sb = sm_nb + EMB*EMB + 2*64*EMB;
    int base = blockIdx.x * 64;
    int t = threadIdx.x;
    for (int i = t; i < EMB*EMB; i += 256) W[i] = w1h[i];
    for (int i = t; i < 64*EMB; i += 256) xs[i] = g_seqh[(size_t)base*EMB + i];
    if (t < 64) sb[t] = 0.0f;
    __syncthreads();
    for (int p = t; p < 64*25; p += 256) {
        int n = p / 25, k4 = p - n*25;
        float a0 = 0.f, a1 = 0.f, a2 = 0.f, a3 = 0.f;
        const float* xr = xs + n*EMB;
        #pragma unroll 4
        for (int j = 0; j < EMB; ++j) {
            float xv = xr[j];
            float4 wv = *(const float4*)&W[j*EMB + k4*4];
            a0 += xv*wv.x; a1 += xv*wv.y; a2 += xv*wv.z; a3 += xv*wv.w;
        }
        int r = base + n;
        int l = r - (r / SEQ) * SEQ;
        float4 pw = *(const float4*)&g_posw[l*EMB + k4*4];
        nh[n*EMB + k4*4 + 0] = tanhf(pw.x + a0);
        nh[n*EMB + k4*4 + 1] = tanhf(pw.y + a1);
        nh[n*EMB + k4*4 + 2] = tanhf(pw.z + a2);
        nh[n*EMB + k4*4 + 3] = tanhf(pw.w + a3);
    }
    __syncthreads();
    for (int i = t; i < EMB*EMB; i += 256) W[i] = g_glu1T[i];
    __syncthreads();
    for (int p = t; p < 64*25; p += 256) {
        int n = p / 25, k4 = p - n*25;
        float a0 = 0.f, a1 = 0.f, a2 = 0.f, a3 = 0.f;
        const float* xr = nh + n*EMB;
        #pragma unroll 4
        for (int j = 0; j < EMB; ++j) {
            float xv = xr[j];
            float4 gv = *(const float4*)&W[j*EMB + k4*4];
            a0 += xv*gv.x; a1 += xv*gv.y; a2 += xv*gv.z; a3 += xv*gv.w;
        }
        int r = base + n;
        int b = r / SEQ;
        float4 hb = *(const float4*)&g_hsg[b*EMB + k4*4];
        float4 bb = *(const float4*)&glu1b[k4*4];
        float4 wv = *(const float4*)&w2[k4*4];
        float c = 0.0f;
        c += wv.x / (1.0f + __expf(-(a0 + bb.x + hb.x)));
        c += wv.y / (1.0f + __expf(-(a1 + bb.y + hb.y)));
        c += wv.z / (1.0f + __expf(-(a2 + bb.z + hb.z)));
        c += wv.w / (1.0f + __expf(-(a3 + bb.w + hb.w)));
        atomicAdd(&sb[n], c);
    }
    __syncthreads();
    if (t < 64) {
        int r = base + t;
        int b = r / SEQ, l = r - b*SEQ;
        g_beta[r] = sb[t] * (float)mask[b*SEQ + l];
    }
}

// ---------------- sess stage 4 ----------------
__global__ void k_sessagg() {
    __shared__ float bet[SEQ];
    int b = blockIdx.x, t = threadIdx.x;
    if (t < SEQ) bet[t] = g_beta[b*SEQ + t];
    __syncthreads();
    if (t < EMB) {
        float s = 0.0f;
        const float* sq = g_seqh + (size_t)b*SEQ*EMB + t;
        #pragma unroll 5
        for (int l = 0; l < SEQ; ++l) s += bet[l] * sq[l*EMB];
        g_sess[b*EMB + t] = s;
    }
}

// ---------------- sess = W_K * l2norm(sess) ----------------
__global__ void k_sess_norm() {
    int gw = (blockIdx.x * blockDim.x + threadIdx.x) >> 5;
    int lane = threadIdx.x & 31;
    if (gw >= BATCH) return;
    float ss = 0.0f;
    float v[4];
    #pragma unroll
    for (int i = 0; i < 4; ++i) {
        int k = lane + 32*i;
        v[i] = (k < EMB) ? g_sess[gw*EMB + k] : 0.0f;
        ss += v[i]*v[i];
    }
    ss = warp_sum(ss);
    float sc = W_KF / fmaxf(sqrtf(ss), EPSN);
    #pragma unroll
    for (int i = 0; i < 4; ++i) {
        int k = lane + 32*i;
        if (k < EMB) g_sessn[gw*EMB + k] = v[i] * sc;
    }
}

// ---------------- scores: 128 items x 64 sessions per block ----------------
#define SC_SMEM ((128*EMB + 64*EMB)*4)
__global__ __launch_bounds__(256) void k_scores(float* __restrict__ scores) {
    extern __shared__ float sm_sc[];
    float* its = sm_sc;
    float* ses = sm_sc + 128*EMB;
    int t = threadIdx.x;
    int nb = blockIdx.x * 128;
    int bb = blockIdx.y * 64;
    for (int i = t; i < 128*EMB; i += 256) {
        int item = nb + i / EMB;
        its[i] = (item < N_NODE) ? g_itemn[(size_t)nb*EMB + i] : 0.0f;
    }
    for (int i = t; i < 64*EMB; i += 256) ses[i] = g_sessn[(size_t)bb*EMB + i];
    __syncthreads();
    int ic = t & 31, sg = t >> 5;
    float acc[8][4];
    #pragma unroll
    for (int j = 0; j < 8; ++j)
        #pragma unroll
        for (int ii = 0; ii < 4; ++ii) acc[j][ii] = 0.0f;
    for (int k4 = 0; k4 < 25; ++k4) {
        float4 iv[4];
        #pragma unroll
        for (int ii = 0; ii < 4; ++ii)
            iv[ii] = *(const float4*)&its[(ic + 32*ii)*EMB + k4*4];
        #pragma unroll
        for (int j = 0; j < 8; ++j) {
            float4 sv = *(const float4*)&ses[(sg*8 + j)*EMB + k4*4];
            #pragma unroll
            for (int ii = 0; ii < 4; ++ii)
                acc[j][ii] += iv[ii].x*sv.x + iv[ii].y*sv.y + iv[ii].z*sv.z + iv[ii].w*sv.w;
        }
    }
    #pragma unroll
    for (int j = 0; j < 8; ++j) {
        int b = bb + sg*8 + j;
        #pragma unroll
        for (int ii = 0; ii < 4; ++ii) {
            int col = nb + ic + 32*ii;
            if (col < N_NODE) scores[(size_t)b * N_NODE + col] = acc[j][ii];
        }
    }
}

// ---------------- loss_item: online CE ----------------
__global__ void k_loss(const float* __restrict__ scores, const int* __restrict__ tar,
                       float* __restrict__ out0) {
    __shared__ float shm[256], shs[256];
    int b = blockIdx.x, t = threadIdx.x;
    const float* row = scores + (size_t)b * N_NODE;
    float m = -INFINITY, s = 0.0f;
    for (int i = t; i < N_NODE; i += 256) {
        float v = row[i];
        if (v > m) { s = s * __expf(m - v) + 1.0f; m = v; }
        else       { s += __expf(v - m); }
    }
    shm[t] = m; shs[t] = s; __syncthreads();
    for (int o = 128; o > 0; o >>= 1) {
        if (t < o) {
            float m2 = shm[t+o], s2 = shs[t+o];
            float M = fmaxf(shm[t], m2);
            shs[t] = shs[t]*__expf(shm[t]-M) + s2*__expf(m2-M);
            shm[t] = M;
        }
        __syncthreads();
    }
    if (t == 0) {
        float lse = shm[0] + logf(shs[0]);
        atomicAdd(out0, (lse - row[tar[b]]) * (1.0f / BATCH));
    }
}

// ---------------- cl GEMM: mma.sync persistent, kc-outer 8-chain ILP, fused top-10 ----------------
__global__ __launch_bounds__(128) void k_cl_tc() {
    extern __shared__ __align__(16) char smraw[];   // A 30720 | B0 30720 | B1 30720
    __shared__ int sh_item;
    uint32_t sbase = (uint32_t)__cvta_generic_to_shared(smraw);
    int t = threadIdx.x, lane = t & 31, w = t >> 5;

    for (;;) {
        __syncthreads();
        if (t == 0) sh_item = atomicAdd(&g_work, 1);
        __syncthreads();
        int item = sh_item;
        if (item >= NITEMS) return;
        int rowblk = item >> 3, q = item & 7;
        int rbase = rowblk * CLM;
        int qs = (q * NT2) / NQ, qe = ((q + 1) * NT2) / NQ;

        const __nv_bfloat16* Ag = g_bf16 + (size_t)rbase * KPAD;
        for (int idx = t; idx < CLM*14; idx += 128) {
            int r = idx / 14, c = idx - r*14;
            *(uint4*)(smraw + (r*BROW + c*8)*2) = *(const uint4*)(Ag + r*KPAD + c*8);
        }
        __syncthreads();

        uint32_t Af[KC][2][4];
        #pragma unroll
        for (int mh = 0; mh < 2; ++mh) {
            uint32_t aaddr = sbase +
                ((unsigned)(w*32 + mh*16 + (lane & 15))*BROW + ((lane >> 4)*8)) * 2;
            #pragma unroll
            for (int kc = 0; kc < KC; ++kc) {
                asm volatile("ldmatrix.sync.aligned.m8n8.x4.shared.b16 {%0,%1,%2,%3}, [%4];"
                    : "=r"(Af[kc][mh][0]), "=r"(Af[kc][mh][1]),
                      "=r"(Af[kc][mh][2]), "=r"(Af[kc][mh][3])
                    : "r"(aaddr + kc*32));
            }
        }
        __syncthreads();

        {
            const __nv_bfloat16* Bg = g_bf16 + (size_t)qs * CLN * KPAD;
            uint32_t dst = sbase + A_BYTES + (uint32_t)(qs & 1) * B_BYTES;
            for (int idx = t; idx < CLN*14; idx += 128) {
                int r = idx / 14, c = idx - r*14;
                uint32_t d = dst + (unsigned)(r*BROW + c*8)*2;
                const void* s = Bg + r*KPAD + c*8;
                asm volatile("cp.async.cg.shared.global [%0], [%1], 16;" :: "r"(d), "l"(s));
            }
            asm volatile("cp.async.commit_group;" ::: "memory");
        }

        float tk0[TOPK], tk1[TOPK], tk2[TOPK], tk3[TOPK];
        #pragma unroll
        for (int i = 0; i < TOPK; ++i) {
            tk0[i] = -INFINITY; tk1[i] = -INFINITY;
            tk2[i] = -INFINITY; tk3[i] = -INFINITY;
        }

        int quad = lane >> 3, r8 = lane & 7;
        uint32_t bth = ((unsigned)(r8 + 8*(quad >> 1))*BROW + (quad & 1)*8) * 2;

        for (int tile = qs; tile < qe; ++tile) {
            asm volatile("cp.async.wait_group 0;" ::: "memory");
            __syncthreads();
            if (tile + 1 < qe) {
                const __nv_bfloat16* Bg = g_bf16 + (size_t)(tile + 1) * CLN * KPAD;
                uint32_t dst = sbase + A_BYTES + (uint32_t)((tile + 1) & 1) * B_BYTES;
                for (int idx = t; idx < CLN*14; idx += 128) {
                    int r = idx / 14, c = idx - r*14;
                    uint32_t d = dst + (unsigned)(r*BROW + c*8)*2;
                    const void* s = Bg + r*KPAD + c*8;
                    asm volatile("cp.async.cg.shared.global [%0], [%1], 16;" :: "r"(d), "l"(s));
                }
                asm volatile("cp.async.commit_group;" ::: "memory");
            }
            uint32_t bb = sbase + A_BYTES + (uint32_t)(tile & 1)*B_BYTES + bth;
            int npairs = (tile == NT2-1) ? 2 : 8;
            // process column-pairs (p, p+1): kc-outer, 8 independent MMA chains
            for (int pp = 0; pp < npairs; pp += 2) {
                uint32_t ba0 = bb + (unsigned)pp*(16*BROW*2);
                uint32_t ba1 = ba0 + (unsigned)(16*BROW*2);
                float acc[2][2][2][4];   // [pi][mh][nhalf][4]
                #pragma unroll
                for (int pi = 0; pi < 2; ++pi)
                    #pragma unroll
                    for (int mh = 0; mh < 2; ++mh)
                        #pragma unroll
                        for (int nhf = 0; nhf < 2; ++nhf)
                            #pragma unroll
                            for (int k = 0; k < 4; ++k) acc[pi][mh][nhf][k] = 0.0f;
                #pragma unroll
                for (int kc = 0; kc < KC; ++kc) {
                    uint32_t B0[4], B1[4];
                    asm volatile("ldmatrix.sync.aligned.m8n8.x4.shared.b16 {%0,%1,%2,%3}, [%4];"
                        : "=r"(B0[0]), "=r"(B0[1]), "=r"(B0[2]), "=r"(B0[3])
                        : "r"(ba0 + kc*32));
                    asm volatile("ldmatrix.sync.aligned.m8n8.x4.shared.b16 {%0,%1,%2,%3}, [%4];"
                        : "=r"(B1[0]), "=r"(B1[1]), "=r"(B1[2]), "=r"(B1[3])
                        : "r"(ba1 + kc*32));
                    #define MMA16816(D, A, Bx, By) \
                        asm volatile("mma.sync.aligned.m16n8k16.row.col.f32.bf16.bf16.f32 " \
                            "{%0,%1,%2,%3}, {%4,%5,%6,%7}, {%8,%9}, {%0,%1,%2,%3};" \
                            : "+f"((D)[0]), "+f"((D)[1]), "+f"((D)[2]), "+f"((D)[3]) \
                            : "r"((A)[0]), "r"((A)[1]), "r"((A)[2]), "r"((A)[3]), \
                              "r"(Bx), "r"(By))
                    MMA16816(acc[0][0][0], Af[kc][0], B0[0], B0[1]);
                    MMA16816(acc[0][0][1], Af[kc][0], B0[2], B0[3]);
                    MMA16816(acc[0][1][0], Af[kc][1], B0[0], B0[1]);
                    MMA16816(acc[0][1][1], Af[kc][1], B0[2], B0[3]);
                    MMA16816(acc[1][0][0], Af[kc][0], B1[0], B1[1]);
                    MMA16816(acc[1][0][1], Af[kc][0], B1[2], B1[3]);
                    MMA16816(acc[1][1][0], Af[kc][1], B1[0], B1[1]);
                    MMA16816(acc[1][1][1], Af[kc][1], B1[2], B1[3]);
                    #undef MMA16816
                }
                // scan: same mapping as before — [nhf][0..1] -> row (lane>>2)(+8), [nhf][2..3] -> +8 list
                #pragma unroll
                for (int pi = 0; pi < 2; ++pi) {
                    #pragma unroll
                    for (int nhf = 0; nhf < 2; ++nhf) {
                        topk_insert(tk0, acc[pi][0][nhf][0]); topk_insert(tk0, acc[pi][0][nhf][1]);
                        topk_insert(tk1, acc[pi][0][nhf][2]); topk_insert(tk1, acc[pi][0][nhf][3]);
                        topk_insert(tk2, acc[pi][1][nhf][0]); topk_insert(tk2, acc[pi][1][nhf][1]);
                        topk_insert(tk3, acc[pi][1][nhf][2]); topk_insert(tk3, acc[pi][1][nhf][3]);
                    }
                }
            }
        }

        __syncthreads();
        float* mg = (float*)smraw;
        int g = lane >> 2, i4 = lane & 3;
        int base_r = w*32 + g;
        #pragma unroll
        for (int qq = 0; qq < TOPK; ++qq) {
            mg[(base_r     )*40 + i4*TOPK + qq] = tk0[qq];
            mg[(base_r + 8 )*40 + i4*TOPK + qq] = tk1[qq];
            mg[(base_r + 16)*40 + i4*TOPK + qq] = tk2[qq];
            mg[(base_r + 24)*40 + i4*TOPK + qq] = tk3[qq];
        }
        __syncthreads();
        {
            int row = rbase + t;
            if (row < N_NODE) {
                float m[TOPK];
                #pragma unroll
                for (int qq = 0; qq < TOPK; ++qq) m[qq] = -INFINITY;
                for (int qq = 0; qq < 4*TOPK; ++qq) topk_insert(m, mg[t*40 + qq]);
                #pragma unroll
                for (int qq = 0; qq < TOPK; ++qq)
                    g_qtk[((size_t)row*NQ + q)*TOPK + qq] = m[qq] * INV_TEMP;
            }
        }
    }
}

// ---------------- cl merge ----------------
__global__ void k_cl_merge(float* __restrict__ out_cl) {
    __shared__ float sh[256];
    int idx = blockIdx.x * 256 + threadIdx.x;
    float contrib = 0.0f;
    if (idx < N_NODE) {
        float m[TOPK];
        #pragma unroll
        for (int q = 0; q < TOPK; ++q) m[q] = -INFINITY;
        const float* p = g_qtk + (size_t)idx*NQ*TOPK;
        for (int q = 0; q < NQ*TOPK; ++q) topk_insert(m, p[q]);
        float se = 0.0f;
        #pragma unroll
        for (int q = 1; q < TOPK; ++q) se += __expf(m[q] - m[0]);
        contrib = log1pf(se) * (CL_WF / (float)N_NODE);
    }
    sh[threadIdx.x] = contrib; __syncthreads();
    for (int s = 128; s > 0; s >>= 1) {
        if (threadIdx.x < s) sh[threadIdx.x] += sh[threadIdx.x + s];
        __syncthreads();
    }
    if (threadIdx.x == 0) atomicAdd(out_cl, sh[0]);
}

// ---------------- launch (single stream — multi-stream capture caused R14 container failure) ----------------
extern "C" void kernel_launch(void* const* d_in, const int* in_sizes, int n_in,
                              void* d_out, int out_size) {
    const float* slen  = (const float*)d_in[1];
    const int*   rev   = (const int*)d_in[2];
    const int*   mask  = (const int*)d_in[3];
    const int*   tar   = (const int*)d_in[5];
    const int*   arow  = (const int*)d_in[8];
    const int*   acol  = (const int*)d_in[9];
    const float* avals = (const float*)d_in[10];
    const float* emb   = (const float*)d_in[11];
    const float* pos   = (const float*)d_in[12];
    const float* witem = (const float*)d_in[13];
    const float* attw  = (const float*)d_in[14];
    const float* attb  = (const float*)d_in[15];
    const float* w1    = (const float*)d_in[16];
    const float* w2    = (const float*)d_in[17];
    const float* glu1  = (const float*)d_in[18];
    const float* glu1b = (const float*)d_in[19];
    const float* glu2  = (const float*)d_in[20];
    float* out = (float*)d_out;
    int E = in_sizes[8];

    cudaFuncSetAttribute(k_cl_tc, cudaFuncAttributeMaxDynamicSharedMemorySize, CL_SMEM);
    cudaFuncSetAttribute(k_scores, cudaFuncAttributeMaxDynamicSharedMemorySize, SC_SMEM);
    cudaFuncSetAttribute(k_lin_att, cudaFuncAttributeMaxDynamicSharedMemorySize,
                         (EMB*EMB + 64*EMB)*4);
    cudaFuncSetAttribute(k_nhbeta, cudaFuncAttributeMaxDynamicSharedMemorySize, NB_SMEM);

    k_init<<<2048, 256>>>(emb, out, out_size);
    k_transpose<<<(N_LAYERS*EMB*EMB + 255)/256, 256>>>(witem, glu1, glu2);
    k_posw<<<SEQ, 128>>>(pos, w1);
    k_prep<<<(E + 255)/256, 256>>>(arow, acol, avals, E);
    k_scan<<<1, 1024>>>();
    k_scatter<<<(E + 255)/256, 256>>>(arow, acol, avals, E);

    for (int l = 0; l < N_LAYERS; ++l) {
        k_att_score<<<(N_NODE*32 + 255)/256, 256>>>(attw, attb);
        k_lin_att<<<(N_NODE + 63)/64, 256, (EMB*EMB + 64*EMB)*4>>>(l);
        k_spmm_csr<<<(N_NODE*32 + 255)/256, 256>>>();
    }

    k_item<<<(N_NODE*32 + 255)/256, 256>>>();

    k_sess_pre<<<BATCH, 128>>>(rev, slen);
    k_nhbeta<<<NROWS_S/64, 256, NB_SMEM>>>(w1 + EMB*EMB, mask, w2, glu1b);
    k_sessagg<<<BATCH, 128>>>();
    k_sess_norm<<<(BATCH*32 + 255)/256, 256>>>();

    dim3 sg((N_NODE + 127)/128, BATCH/64);
    k_scores<<<sg, 256, SC_SMEM>>>(out + 1);
    k_loss<<<BATCH, 256>>>(out + 1, tar, out);

    k_cl_tc<<<CLGRID, 128, CL_SMEM>>>();
    k_cl_merge<<<(N_NODE + 255)/256, 256>>>(out + out_size - 1);
}